// round 6
// baseline (speedup 1.0000x reference)
#include <cuda_runtime.h>
#include <cuda_bf16.h>
#include <cstdint>
#include <math.h>

#define BATCH  2
#define SEQ    2048
#define EMBED  1024
#define NHEADS 16
#define HDIM   64
#define MROWS  4096
#define MATSZ  (MROWS*EMBED)     // 4194304
#define WSZ    (EMBED*EMBED)     // 1048576

// ---------------------------------------------------------------------------
// Scratch planes (__device__ globals; allocation-free rule)
// ---------------------------------------------------------------------------
__device__ __nv_bfloat16 g_xh[MATSZ],  g_xl[MATSZ];     // x split      [M,K]
__device__ __nv_bfloat16 g_wh[4*WSZ],  g_wl[4*WSZ];     // W^T split    [N,K] (q,k,v,o)
__device__ __nv_bfloat16 g_qkvh[3*MATSZ], g_qkvl[3*MATSZ]; // q,k,v [B,H,S,D]
__device__ __nv_bfloat16 g_ah[MATSZ],  g_al[MATSZ];     // attn out     [M,E]

// ---------------------------------------------------------------------------
// Helpers
// ---------------------------------------------------------------------------
__device__ __forceinline__ uint32_t s2u(const void* p){
    uint32_t a;
    asm("{ .reg .u64 t; cvta.to.shared.u64 t, %1; cvt.u32.u64 %0, t; }" : "=r"(a) : "l"(p));
    return a;
}
__device__ __forceinline__ uint32_t pack2(float lo, float hi){
    __nv_bfloat162 v = __halves2bfloat162(__float2bfloat16(lo), __float2bfloat16(hi));
    return *reinterpret_cast<uint32_t*>(&v);
}
__device__ __forceinline__ void ldsm4(uint32_t& r0,uint32_t& r1,uint32_t& r2,uint32_t& r3,uint32_t a){
    asm volatile("ldmatrix.sync.aligned.m8n8.x4.shared.b16 {%0,%1,%2,%3}, [%4];"
        : "=r"(r0),"=r"(r1),"=r"(r2),"=r"(r3) : "r"(a));
}
__device__ __forceinline__ void ldsm4t(uint32_t& r0,uint32_t& r1,uint32_t& r2,uint32_t& r3,uint32_t a){
    asm volatile("ldmatrix.sync.aligned.m8n8.x4.trans.shared.b16 {%0,%1,%2,%3}, [%4];"
        : "=r"(r0),"=r"(r1),"=r"(r2),"=r"(r3) : "r"(a));
}
__device__ __forceinline__ void mma_bf16(float* c, const uint32_t* a, const uint32_t* b){
    asm volatile("mma.sync.aligned.m16n8k16.row.col.f32.bf16.bf16.f32 "
        "{%0,%1,%2,%3}, {%4,%5,%6,%7}, {%8,%9}, {%0,%1,%2,%3};"
        : "+f"(c[0]),"+f"(c[1]),"+f"(c[2]),"+f"(c[3])
        : "r"(a[0]),"r"(a[1]),"r"(a[2]),"r"(a[3]), "r"(b[0]),"r"(b[1]));
}
__device__ __forceinline__ void cpa16(uint32_t dst, const void* src){
    asm volatile("cp.async.cg.shared.global [%0], [%1], 16;" :: "r"(dst), "l"(src));
}
#define CPCOMMIT() asm volatile("cp.async.commit_group;" ::: "memory")
#define CPWAIT0()  asm volatile("cp.async.wait_group 0;" ::: "memory")
#define CPWAIT1()  asm volatile("cp.async.wait_group 1;" ::: "memory")

// FMA-only exp (x <= 0 path): ~3e-6 rel err, no MUFU.
__device__ __forceinline__ float fexp(float x){
    float y = x * 1.4426950408889634f;
    y = fmaxf(y, -126.0f);
    float t = y + 12582912.0f;               // round-to-nearest
    int   n = __float_as_int(t) - 0x4B400000;
    float f = y - (t - 12582912.0f);         // f in [-0.5, 0.5]
    float p = 1.3333558146e-3f;
    p = fmaf(p, f, 9.6181291076e-3f);
    p = fmaf(p, f, 5.5504108665e-2f);
    p = fmaf(p, f, 2.4022650696e-1f);
    p = fmaf(p, f, 6.9314718056e-1f);
    p = fmaf(p, f, 1.0f);
    return __int_as_float(__float_as_int(p) + (n << 23));
}

// ---------------------------------------------------------------------------
// Prep: split x -> bf16 hi/lo planes
// ---------------------------------------------------------------------------
__global__ __launch_bounds__(256) void splitx_kernel(const float* __restrict__ x)
{
    int i = blockIdx.x*256 + threadIdx.x;    // float4 index, 1048576 total
    float4 v = ((const float4*)x)[i];
    uint32_t h0 = pack2(v.x, v.y), h1 = pack2(v.z, v.w);
    float hx = __uint_as_float(h0 << 16), hy = __uint_as_float(h0 & 0xffff0000u);
    float hz = __uint_as_float(h1 << 16), hw = __uint_as_float(h1 & 0xffff0000u);
    uint32_t l0 = pack2(v.x - hx, v.y - hy), l1 = pack2(v.z - hz, v.w - hw);
    ((uint2*)g_xh)[i] = make_uint2(h0, h1);
    ((uint2*)g_xl)[i] = make_uint2(l0, l1);
}

// ---------------------------------------------------------------------------
// Prep: transpose W [K,N] -> W^T [N,K], split to bf16 hi/lo. z: 0..3 = q,k,v,o
// ---------------------------------------------------------------------------
__global__ __launch_bounds__(256) void wprep_kernel(
    const float* __restrict__ Wq, const float* __restrict__ Wk,
    const float* __restrict__ Wv, const float* __restrict__ Wo)
{
    __shared__ float t[32][33];
    int z = blockIdx.z;
    const float* W = (z==0)?Wq:(z==1)?Wk:(z==2)?Wv:Wo;
    __nv_bfloat16* Oh = g_wh + (size_t)z*WSZ;
    __nv_bfloat16* Ol = g_wl + (size_t)z*WSZ;
    int nb = blockIdx.x*32, kb = blockIdx.y*32;
    int tx = threadIdx.x, ty = threadIdx.y;
    #pragma unroll
    for (int r = 0; r < 4; r++)
        t[ty + r*8][tx] = W[(size_t)(kb + ty + r*8)*EMBED + nb + tx];
    __syncthreads();
    #pragma unroll
    for (int r = 0; r < 4; r++) {
        float v = t[tx][ty + r*8];
        __nv_bfloat16 hb = __float2bfloat16(v);
        size_t o = (size_t)(nb + ty + r*8)*EMBED + kb + tx;
        Oh[o] = hb;
        Ol[o] = __float2bfloat16(v - __bfloat162float(hb));
    }
}

// ---------------------------------------------------------------------------
// mma.sync bf16 3-term split GEMM: D[M,N] = A[M,K] @ B^T[N,K]
// CTA 128x128, 8 warps (4m x 2n), warp 32x64, KC=32, 3-stage cp.async.
// mode 0: A = x planes, B = W_{q,k,v}(z), epilogue -> bf16 hi/lo qkv planes
// mode 1: A = attn planes, B = W_o, epilogue -> fp32 out + bias
// ---------------------------------------------------------------------------
#define GKC 32
#define GPITCH 80
#define GPLANE (128*GPITCH)      // 10240
#define GSTAGE (4*GPLANE)        // 40960
#define GSMEM  (3*GSTAGE)        // 122880

__global__ __launch_bounds__(256,1) void gemm_kernel(float* __restrict__ out,
                                                     const float* __restrict__ bias,
                                                     int mode)
{
    extern __shared__ char smg[];
    const uint32_t sb = s2u(smg);
    const int tid = threadIdx.x, l = tid & 31, wid = tid >> 5;
    const int wm = wid >> 1, wn = wid & 1;
    const int m0 = blockIdx.y * 128, n0 = blockIdx.x * 128;
    const int z = blockIdx.z;

    const __nv_bfloat16 *Ah, *Al, *Bh, *Bl;
    if (mode == 0) {
        Ah = g_xh; Al = g_xl;
        Bh = g_wh + (size_t)z*WSZ; Bl = g_wl + (size_t)z*WSZ;
    } else {
        Ah = g_ah; Al = g_al;
        Bh = g_wh + 3*(size_t)WSZ; Bl = g_wl + 3*(size_t)WSZ;
    }

    auto load_stage = [&](int c){
        const uint32_t sbase = sb + (c % 3)*GSTAGE;
        const int k0 = c * GKC;
        #pragma unroll
        for (int i = 0; i < 8; i++) {
            int g   = i*256 + tid;        // 0..2047
            int p   = g >> 9;             // 0:Ah 1:Al 2:Bh 3:Bl
            int row = (g >> 2) & 127;
            int ch  = g & 3;
            const __nv_bfloat16* src = (p==0)?Ah:(p==1)?Al:(p==2)?Bh:Bl;
            int grow = (p < 2 ? m0 : n0) + row;
            cpa16(sbase + p*GPLANE + row*GPITCH + ch*16,
                  src + (size_t)grow*EMBED + k0 + ch*8);
        }
        CPCOMMIT();
    };

    float acc[2][8][4];
    #pragma unroll
    for (int i = 0; i < 2; i++)
        #pragma unroll
        for (int t = 0; t < 8; t++)
            #pragma unroll
            for (int j = 0; j < 4; j++) acc[i][t][j] = 0.f;

    load_stage(0);
    load_stage(1);
    for (int c = 0; c < 32; c++) {
        if (c < 31) { CPWAIT1(); } else { CPWAIT0(); }
        __syncthreads();
        if (c + 2 < 32) load_stage(c + 2);
        const uint32_t stb = sb + (c % 3)*GSTAGE;
        #pragma unroll
        for (int kk = 0; kk < 2; kk++) {
            uint32_t ah[2][4], al[2][4], bhf[8][2], blf[8][2];
            #pragma unroll
            for (int i = 0; i < 2; i++) {
                int row = 32*wm + 16*i + (l & 15);
                int ko  = kk*16 + ((l >> 4) << 3);
                uint32_t off = (uint32_t)(row*GPITCH + ko*2);
                ldsm4(ah[i][0],ah[i][1],ah[i][2],ah[i][3], stb + 0*GPLANE + off);
                ldsm4(al[i][0],al[i][1],al[i][2],al[i][3], stb + 1*GPLANE + off);
            }
            #pragma unroll
            for (int tp = 0; tp < 4; tp++) {
                int nrow = 64*wn + 16*tp + ((l>>4)<<3) + (l & 7);
                int ko   = kk*16 + (((l>>3)&1) << 3);
                uint32_t off = (uint32_t)(nrow*GPITCH + ko*2);
                ldsm4(bhf[2*tp][0],bhf[2*tp][1],bhf[2*tp+1][0],bhf[2*tp+1][1], stb + 2*GPLANE + off);
                ldsm4(blf[2*tp][0],blf[2*tp][1],blf[2*tp+1][0],blf[2*tp+1][1], stb + 3*GPLANE + off);
            }
            // term-major ordering -> long accumulator reuse distance
            #pragma unroll
            for (int i = 0; i < 2; i++)
                #pragma unroll
                for (int t = 0; t < 8; t++) mma_bf16(acc[i][t], ah[i], bhf[t]);
            #pragma unroll
            for (int i = 0; i < 2; i++)
                #pragma unroll
                for (int t = 0; t < 8; t++) mma_bf16(acc[i][t], ah[i], blf[t]);
            #pragma unroll
            for (int i = 0; i < 2; i++)
                #pragma unroll
                for (int t = 0; t < 8; t++) mma_bf16(acc[i][t], al[i], bhf[t]);
        }
    }

    // epilogue
    if (mode == 1) {
        #pragma unroll
        for (int i = 0; i < 2; i++)
            #pragma unroll
            for (int t = 0; t < 8; t++)
                #pragma unroll
                for (int rr = 0; rr < 2; rr++) {
                    int m = m0 + 32*wm + 16*i + (l>>2) + 8*rr;
                    int n = n0 + 64*wn + 8*t + 2*(l&3);
                    float2 v = make_float2(acc[i][t][2*rr]   + bias[n],
                                           acc[i][t][2*rr+1] + bias[n+1]);
                    *(float2*)&out[(size_t)m*EMBED + n] = v;
                }
    } else {
        __nv_bfloat16* oh = g_qkvh + (size_t)z*MATSZ;
        __nv_bfloat16* ol = g_qkvl + (size_t)z*MATSZ;
        const float scl = (z == 0) ? 0.125f : 1.0f;   // fold 1/sqrt(D) into Q
        #pragma unroll
        for (int i = 0; i < 2; i++)
            #pragma unroll
            for (int t = 0; t < 8; t++)
                #pragma unroll
                for (int rr = 0; rr < 2; rr++) {
                    int m = m0 + 32*wm + 16*i + (l>>2) + 8*rr;
                    int n = n0 + 64*wn + 8*t + 2*(l&3);
                    float v0 = acc[i][t][2*rr]*scl, v1 = acc[i][t][2*rr+1]*scl;
                    uint32_t h = pack2(v0, v1);
                    float h0 = __uint_as_float(h << 16);
                    float h1 = __uint_as_float(h & 0xffff0000u);
                    uint32_t lo = pack2(v0 - h0, v1 - h1);
                    int b = m >> 11, s = m & 2047, hh = n >> 6, d = n & 63;
                    size_t idx = ((((size_t)b*NHEADS + hh)*SEQ) + s)*HDIM + d;
                    *(uint32_t*)(oh + idx) = h;
                    *(uint32_t*)(ol + idx) = lo;
                }
    }
}

// ---------------------------------------------------------------------------
// Flash attention via mma.sync. CTA = 64 q-rows of one (b,h); 4 warps = m16 each.
// 128 threads, 92KB smem -> 2 CTAs/SM for cross-CTA latency hiding.
// K-tiles of 64 keys, 2-stage cp.async. P kept in registers (FA2 style).
// ---------------------------------------------------------------------------
#define APITCH 144
#define AQPL   (64*APITCH)         // 9216
#define AKPL   (64*APITCH)         // 9216
#define ASTAGE (4*AKPL)            // 36864
#define ASMEM  (2*AQPL + 2*ASTAGE) // 92160

__global__ __launch_bounds__(128,2) void attn_kernel()
{
    extern __shared__ char sma[];
    const uint32_t sb = s2u(sma);
    const int tid = threadIdx.x, l = tid & 31, wid = tid >> 5;
    const int qt = 31 - (int)blockIdx.x;        // heavy tiles first
    const int bh = blockIdx.y;
    const int q0 = qt * 64;
    const int nkt = qt + 1;
    const size_t base = (size_t)bh * SEQ * HDIM;
    const __nv_bfloat16 *Qh = g_qkvh + base,              *Ql = g_qkvl + base;
    const __nv_bfloat16 *Kh = g_qkvh + MATSZ + base,      *Kl = g_qkvl + MATSZ + base;
    const __nv_bfloat16 *Vh = g_qkvh + 2*(size_t)MATSZ + base,
                        *Vl = g_qkvl + 2*(size_t)MATSZ + base;

    const uint32_t sQh = sb, sQl = sb + AQPL;
    const uint32_t skv0 = sb + 2*AQPL;

    // Q tile loads (64 rows x 2 planes), 1024 cp.async over 128 threads
    #pragma unroll
    for (int i = 0; i < 8; i++) {
        int g = i*128 + tid;
        int p = g >> 9, row = (g >> 3) & 63, ch = g & 7;
        const __nv_bfloat16* src = p ? Ql : Qh;
        cpa16((p ? sQl : sQh) + row*APITCH + ch*16,
              src + (size_t)(q0 + row)*HDIM + ch*8);
    }
    CPCOMMIT();

    auto load_kv = [&](int kt){
        const uint32_t stb = skv0 + (kt & 1)*ASTAGE;
        const int k0 = kt * 64;
        #pragma unroll
        for (int i = 0; i < 16; i++) {
            int g = i*128 + tid;
            int p = g >> 9, row = (g >> 3) & 63, ch = g & 7;  // p: 0 Kh 1 Kl 2 Vh 3 Vl
            const __nv_bfloat16* src = (p==0)?Kh:(p==1)?Kl:(p==2)?Vh:Vl;
            cpa16(stb + p*AKPL + row*APITCH + ch*16,
                  src + (size_t)(k0 + row)*HDIM + ch*8);
        }
        CPCOMMIT();
    };
    load_kv(0);
    CPWAIT0();
    __syncthreads();

    // Q fragments register-resident (rows 16*wid .. +15, 4 k16 chunks)
    uint32_t qfh[4][4], qfl[4][4];
    {
        int row = 16*wid + (l & 15);
        #pragma unroll
        for (int kc = 0; kc < 4; kc++) {
            int ko = kc*16 + ((l >> 4) << 3);
            uint32_t off = (uint32_t)(row*APITCH + ko*2);
            ldsm4(qfh[kc][0],qfh[kc][1],qfh[kc][2],qfh[kc][3], sQh + off);
            ldsm4(qfl[kc][0],qfl[kc][1],qfl[kc][2],qfl[kc][3], sQl + off);
        }
    }

    float o[8][4];
    #pragma unroll
    for (int t = 0; t < 8; t++)
        #pragma unroll
        for (int j = 0; j < 4; j++) o[t][j] = 0.f;
    float mr0 = -1e30f, mr1 = -1e30f, lr0 = 0.f, lr1 = 0.f;
    const int qg0 = q0 + 16*wid + (l >> 2);
    const int qg1 = qg0 + 8;

    for (int kt = 0; kt < nkt; kt++) {
        if (kt + 1 < nkt) load_kv(kt + 1);
        const uint32_t stb = skv0 + (kt & 1)*ASTAGE;
        const int k0 = kt * 64;

        {
            // ---- S = Q K^T (3-term) ----
            float s[8][4];
            #pragma unroll
            for (int t = 0; t < 8; t++)
                #pragma unroll
                for (int j = 0; j < 4; j++) s[t][j] = 0.f;
            #pragma unroll
            for (int kc = 0; kc < 4; kc++) {
                uint32_t bhf[8][2], blf[8][2];
                #pragma unroll
                for (int tp = 0; tp < 4; tp++) {
                    int nrow = 16*tp + ((l>>4)<<3) + (l & 7);
                    int ko   = kc*16 + (((l>>3)&1) << 3);
                    uint32_t off = (uint32_t)(nrow*APITCH + ko*2);
                    ldsm4(bhf[2*tp][0],bhf[2*tp][1],bhf[2*tp+1][0],bhf[2*tp+1][1], stb + 0*AKPL + off);
                    ldsm4(blf[2*tp][0],blf[2*tp][1],blf[2*tp+1][0],blf[2*tp+1][1], stb + 1*AKPL + off);
                }
                #pragma unroll
                for (int t = 0; t < 8; t++) mma_bf16(s[t], qfh[kc], bhf[t]);
                #pragma unroll
                for (int t = 0; t < 8; t++) mma_bf16(s[t], qfh[kc], blf[t]);
                #pragma unroll
                for (int t = 0; t < 8; t++) mma_bf16(s[t], qfl[kc], bhf[t]);
            }
            // ---- causal mask (only near diagonal) ----
            if (k0 + 63 > qg0) {
                #pragma unroll
                for (int t = 0; t < 8; t++) {
                    int kg = k0 + 8*t + 2*(l & 3);
                    if (kg     > qg0) s[t][0] = -1e30f;
                    if (kg + 1 > qg0) s[t][1] = -1e30f;
                    if (kg     > qg1) s[t][2] = -1e30f;
                    if (kg + 1 > qg1) s[t][3] = -1e30f;
                }
            }
            // ---- online softmax (rows qg0, qg1) ----
            float mx0 = -1e30f, mx1 = -1e30f;
            #pragma unroll
            for (int t = 0; t < 8; t++) {
                mx0 = fmaxf(mx0, fmaxf(s[t][0], s[t][1]));
                mx1 = fmaxf(mx1, fmaxf(s[t][2], s[t][3]));
            }
            mx0 = fmaxf(mx0, __shfl_xor_sync(0xffffffffu, mx0, 1));
            mx0 = fmaxf(mx0, __shfl_xor_sync(0xffffffffu, mx0, 2));
            mx1 = fmaxf(mx1, __shfl_xor_sync(0xffffffffu, mx1, 1));
            mx1 = fmaxf(mx1, __shfl_xor_sync(0xffffffffu, mx1, 2));
            float mn0 = fmaxf(mr0, mx0), mn1 = fmaxf(mr1, mx1);
            float a0 = fexp(mr0 - mn0), a1 = fexp(mr1 - mn1);
            mr0 = mn0; mr1 = mn1;
            float rs0 = 0.f, rs1 = 0.f;
            #pragma unroll
            for (int t = 0; t < 8; t++) {
                s[t][0] = fexp(s[t][0] - mn0);
                s[t][1] = fexp(s[t][1] - mn0);
                s[t][2] = fexp(s[t][2] - mn1);
                s[t][3] = fexp(s[t][3] - mn1);
                rs0 += s[t][0] + s[t][1];
                rs1 += s[t][2] + s[t][3];
            }
            rs0 += __shfl_xor_sync(0xffffffffu, rs0, 1);
            rs0 += __shfl_xor_sync(0xffffffffu, rs0, 2);
            rs1 += __shfl_xor_sync(0xffffffffu, rs1, 1);
            rs1 += __shfl_xor_sync(0xffffffffu, rs1, 2);
            lr0 = lr0*a0 + rs0;
            lr1 = lr1*a1 + rs1;
            #pragma unroll
            for (int t = 0; t < 8; t++) {
                o[t][0] *= a0; o[t][1] *= a0; o[t][2] *= a1; o[t][3] *= a1;
            }
            // ---- P -> bf16 hi/lo A-fragments (registers only) ----
            uint32_t ph[4][4], pl[4][4];
            #pragma unroll
            for (int kc = 0; kc < 4; kc++) {
                int t0 = 2*kc, t1 = t0 + 1;
                float pv[4][2] = {{s[t0][0],s[t0][1]},{s[t0][2],s[t0][3]},
                                  {s[t1][0],s[t1][1]},{s[t1][2],s[t1][3]}};
                #pragma unroll
                for (int r = 0; r < 4; r++) {
                    uint32_t h = pack2(pv[r][0], pv[r][1]);
                    float h0 = __uint_as_float(h << 16);
                    float h1 = __uint_as_float(h & 0xffff0000u);
                    ph[kc][r] = h;
                    pl[kc][r] = pack2(pv[r][0] - h0, pv[r][1] - h1);
                }
            }
            // ---- O += P V (3-term), V via ldmatrix.trans ----
            #pragma unroll
            for (int kc = 0; kc < 4; kc++) {
                uint32_t vhf[8][2], vlf[8][2];
                #pragma unroll
                for (int tp = 0; tp < 4; tp++) {
                    int row = kc*16 + ((l>>3)&1)*8 + (l & 7);
                    int co  = 16*tp + ((l >> 4) << 3);
                    uint32_t off = (uint32_t)(row*APITCH + co*2);
                    ldsm4t(vhf[2*tp][0],vhf[2*tp][1],vhf[2*tp+1][0],vhf[2*tp+1][1], stb + 2*AKPL + off);
                    ldsm4t(vlf[2*tp][0],vlf[2*tp][1],vlf[2*tp+1][0],vlf[2*tp+1][1], stb + 3*AKPL + off);
                }
                #pragma unroll
                for (int t = 0; t < 8; t++) mma_bf16(o[t], ph[kc], vhf[t]);
                #pragma unroll
                for (int t = 0; t < 8; t++) mma_bf16(o[t], ph[kc], vlf[t]);
                #pragma unroll
                for (int t = 0; t < 8; t++) mma_bf16(o[t], pl[kc], vhf[t]);
            }
        }
        if (kt + 1 < nkt) { CPWAIT0(); __syncthreads(); }
    }

    // ---- epilogue: normalize, split to bf16 hi/lo, write [B,S,E] planes ----
    const float inv0 = 1.f / lr0, inv1 = 1.f / lr1;
    const int b = bh >> 4, h = bh & 15;
    const int s0 = qg0, s1 = qg1;
    #pragma unroll
    for (int t = 0; t < 8; t++) {
        int d = 8*t + 2*(l & 3);
        int e = h*HDIM + d;
        {
            float v0 = o[t][0]*inv0, v1 = o[t][1]*inv0;
            uint32_t hh = pack2(v0, v1);
            float h0 = __uint_as_float(hh << 16), h1 = __uint_as_float(hh & 0xffff0000u);
            uint32_t ll = pack2(v0 - h0, v1 - h1);
            size_t idx = ((size_t)b*SEQ + s0)*EMBED + e;
            *(uint32_t*)(g_ah + idx) = hh;
            *(uint32_t*)(g_al + idx) = ll;
        }
        {
            float v0 = o[t][2]*inv1, v1 = o[t][3]*inv1;
            uint32_t hh = pack2(v0, v1);
            float h0 = __uint_as_float(hh << 16), h1 = __uint_as_float(hh & 0xffff0000u);
            uint32_t ll = pack2(v0 - h0, v1 - h1);
            size_t idx = ((size_t)b*SEQ + s1)*EMBED + e;
            *(uint32_t*)(g_ah + idx) = hh;
            *(uint32_t*)(g_al + idx) = ll;
        }
    }
}

// ---------------------------------------------------------------------------
extern "C" void kernel_launch(void* const* d_in, const int* in_sizes, int n_in,
                              void* d_out, int out_size)
{
    const float* x  = (const float*)d_in[0];
    const float* Wq = (const float*)d_in[1];
    const float* Wk = (const float*)d_in[2];
    const float* Wv = (const float*)d_in[3];
    const float* Wo = (const float*)d_in[4];
    const float* bo = (const float*)d_in[5];
    float* out = (float*)d_out;

    cudaFuncSetAttribute(gemm_kernel, cudaFuncAttributeMaxDynamicSharedMemorySize, GSMEM);
    cudaFuncSetAttribute(attn_kernel, cudaFuncAttributeMaxDynamicSharedMemorySize, ASMEM);

    splitx_kernel<<<4096, 256>>>(x);
    wprep_kernel<<<dim3(32, 32, 4), dim3(32, 8)>>>(Wq, Wk, Wv, Wo);

    gemm_kernel<<<dim3(8, 32, 3), 256, GSMEM>>>(nullptr, nullptr, 0);  // QKV
    attn_kernel<<<dim3(32, 32), 128, ASMEM>>>();                       // attention
    gemm_kernel<<<dim3(8, 32, 1), 256, GSMEM>>>(out, bo, 1);           // O-proj
}

// round 8
// speedup vs baseline: 1.0366x; 1.0366x over previous
#include <cuda_runtime.h>
#include <cuda_bf16.h>
#include <cstdint>
#include <math.h>

#define BATCH  2
#define SEQ    2048
#define EMBED  1024
#define NHEADS 16
#define HDIM   64
#define MROWS  4096
#define MATSZ  (MROWS*EMBED)     // 4194304
#define WSZ    (EMBED*EMBED)     // 1048576

// ---------------------------------------------------------------------------
// Scratch planes (__device__ globals; allocation-free rule)
// ---------------------------------------------------------------------------
__device__ __nv_bfloat16 g_xh[MATSZ],  g_xl[MATSZ];     // x split      [M,K]
__device__ __nv_bfloat16 g_wh[4*WSZ],  g_wl[4*WSZ];     // W^T split    [N,K] (q,k,v,o)
__device__ __nv_bfloat16 g_qkvh[3*MATSZ], g_qkvl[3*MATSZ]; // q,k,v [B,H,S,D]
__device__ __nv_bfloat16 g_ah[MATSZ],  g_al[MATSZ];     // attn out     [M,E]

// ---------------------------------------------------------------------------
// Helpers
// ---------------------------------------------------------------------------
__device__ __forceinline__ uint32_t s2u(const void* p){
    uint32_t a;
    asm("{ .reg .u64 t; cvta.to.shared.u64 t, %1; cvt.u32.u64 %0, t; }" : "=r"(a) : "l"(p));
    return a;
}
__device__ __forceinline__ uint32_t pack2(float lo, float hi){
    __nv_bfloat162 v = __halves2bfloat162(__float2bfloat16(lo), __float2bfloat16(hi));
    return *reinterpret_cast<uint32_t*>(&v);
}
__device__ __forceinline__ void ldsm4(uint32_t& r0,uint32_t& r1,uint32_t& r2,uint32_t& r3,uint32_t a){
    asm volatile("ldmatrix.sync.aligned.m8n8.x4.shared.b16 {%0,%1,%2,%3}, [%4];"
        : "=r"(r0),"=r"(r1),"=r"(r2),"=r"(r3) : "r"(a));
}
__device__ __forceinline__ void ldsm4t(uint32_t& r0,uint32_t& r1,uint32_t& r2,uint32_t& r3,uint32_t a){
    asm volatile("ldmatrix.sync.aligned.m8n8.x4.trans.shared.b16 {%0,%1,%2,%3}, [%4];"
        : "=r"(r0),"=r"(r1),"=r"(r2),"=r"(r3) : "r"(a));
}
__device__ __forceinline__ void mma_bf16(float* c, const uint32_t* a, const uint32_t* b){
    asm volatile("mma.sync.aligned.m16n8k16.row.col.f32.bf16.bf16.f32 "
        "{%0,%1,%2,%3}, {%4,%5,%6,%7}, {%8,%9}, {%0,%1,%2,%3};"
        : "+f"(c[0]),"+f"(c[1]),"+f"(c[2]),"+f"(c[3])
        : "r"(a[0]),"r"(a[1]),"r"(a[2]),"r"(a[3]), "r"(b[0]),"r"(b[1]));
}
__device__ __forceinline__ void cpa16(uint32_t dst, const void* src){
    asm volatile("cp.async.cg.shared.global [%0], [%1], 16;" :: "r"(dst), "l"(src));
}
#define CPCOMMIT() asm volatile("cp.async.commit_group;" ::: "memory")
#define CPWAIT0()  asm volatile("cp.async.wait_group 0;" ::: "memory")

// FMA-only exp (x <= 0 path): ~3e-6 rel err, no MUFU.
__device__ __forceinline__ float fexp(float x){
    float y = x * 1.4426950408889634f;
    y = fmaxf(y, -126.0f);
    float t = y + 12582912.0f;               // round-to-nearest
    int   n = __float_as_int(t) - 0x4B400000;
    float f = y - (t - 12582912.0f);         // f in [-0.5, 0.5]
    float p = 1.3333558146e-3f;
    p = fmaf(p, f, 9.6181291076e-3f);
    p = fmaf(p, f, 5.5504108665e-2f);
    p = fmaf(p, f, 2.4022650696e-1f);
    p = fmaf(p, f, 6.9314718056e-1f);
    p = fmaf(p, f, 1.0f);
    return __int_as_float(__float_as_int(p) + (n << 23));
}

// ---------------------------------------------------------------------------
// Prep: split x -> bf16 hi/lo planes
// ---------------------------------------------------------------------------
__global__ __launch_bounds__(256) void splitx_kernel(const float* __restrict__ x)
{
    int i = blockIdx.x*256 + threadIdx.x;    // float4 index, 1048576 total
    float4 v = ((const float4*)x)[i];
    uint32_t h0 = pack2(v.x, v.y), h1 = pack2(v.z, v.w);
    float hx = __uint_as_float(h0 << 16), hy = __uint_as_float(h0 & 0xffff0000u);
    float hz = __uint_as_float(h1 << 16), hw = __uint_as_float(h1 & 0xffff0000u);
    uint32_t l0 = pack2(v.x - hx, v.y - hy), l1 = pack2(v.z - hz, v.w - hw);
    ((uint2*)g_xh)[i] = make_uint2(h0, h1);
    ((uint2*)g_xl)[i] = make_uint2(l0, l1);
}

// ---------------------------------------------------------------------------
// Prep: transpose W [K,N] -> W^T [N,K], split to bf16 hi/lo. z: 0..3 = q,k,v,o
// ---------------------------------------------------------------------------
__global__ __launch_bounds__(256) void wprep_kernel(
    const float* __restrict__ Wq, const float* __restrict__ Wk,
    const float* __restrict__ Wv, const float* __restrict__ Wo)
{
    __shared__ float t[32][33];
    int z = blockIdx.z;
    const float* W = (z==0)?Wq:(z==1)?Wk:(z==2)?Wv:Wo;
    __nv_bfloat16* Oh = g_wh + (size_t)z*WSZ;
    __nv_bfloat16* Ol = g_wl + (size_t)z*WSZ;
    int nb = blockIdx.x*32, kb = blockIdx.y*32;
    int tx = threadIdx.x, ty = threadIdx.y;
    #pragma unroll
    for (int r = 0; r < 4; r++)
        t[ty + r*8][tx] = W[(size_t)(kb + ty + r*8)*EMBED + nb + tx];
    __syncthreads();
    #pragma unroll
    for (int r = 0; r < 4; r++) {
        float v = t[tx][ty + r*8];
        __nv_bfloat16 hb = __float2bfloat16(v);
        size_t o = (size_t)(nb + ty + r*8)*EMBED + kb + tx;
        Oh[o] = hb;
        Ol[o] = __float2bfloat16(v - __bfloat162float(hb));
    }
}

// ---------------------------------------------------------------------------
// mma.sync bf16 3-term split GEMM: D[M,N] = A[M,K] @ B^T[N,K]
// CTA 128x128, 512 threads, 16 warps (4m x 4n), warp 32x32, KC=32, 2-stage.
// 16 warps/SM (4 per scheduler) for issue-latency hiding.
// mode 0: A = x planes, B = W_{q,k,v}(z), epilogue -> bf16 hi/lo qkv planes
// mode 1: A = attn planes, B = W_o, epilogue -> fp32 out + bias
// ---------------------------------------------------------------------------
#define GKC 32
#define GPITCH 80
#define GPLANE (128*GPITCH)      // 10240
#define GSTAGE (4*GPLANE)        // 40960
#define GSMEM  (2*GSTAGE)        // 81920

__global__ __launch_bounds__(512,1) void gemm_kernel(float* __restrict__ out,
                                                     const float* __restrict__ bias,
                                                     int mode)
{
    extern __shared__ char smg[];
    const uint32_t sb = s2u(smg);
    const int tid = threadIdx.x, l = tid & 31, wid = tid >> 5;
    const int wm = wid >> 2, wn = wid & 3;
    const int m0 = blockIdx.y * 128, n0 = blockIdx.x * 128;
    const int z = blockIdx.z;

    const __nv_bfloat16 *Ah, *Al, *Bh, *Bl;
    if (mode == 0) {
        Ah = g_xh; Al = g_xl;
        Bh = g_wh + (size_t)z*WSZ; Bl = g_wl + (size_t)z*WSZ;
    } else {
        Ah = g_ah; Al = g_al;
        Bh = g_wh + 3*(size_t)WSZ; Bl = g_wl + 3*(size_t)WSZ;
    }

    auto load_stage = [&](int c){
        const uint32_t sbase = sb + (c & 1)*GSTAGE;
        const int k0 = c * GKC;
        #pragma unroll
        for (int i = 0; i < 4; i++) {
            int g   = i*512 + tid;        // 0..2047
            int p   = g >> 9;             // 0:Ah 1:Al 2:Bh 3:Bl
            int row = (g >> 2) & 127;
            int ch  = g & 3;
            const __nv_bfloat16* src = (p==0)?Ah:(p==1)?Al:(p==2)?Bh:Bl;
            int grow = (p < 2 ? m0 : n0) + row;
            cpa16(sbase + p*GPLANE + row*GPITCH + ch*16,
                  src + (size_t)grow*EMBED + k0 + ch*8);
        }
        CPCOMMIT();
    };

    float acc[2][4][4];
    #pragma unroll
    for (int i = 0; i < 2; i++)
        #pragma unroll
        for (int t = 0; t < 4; t++)
            #pragma unroll
            for (int j = 0; j < 4; j++) acc[i][t][j] = 0.f;

    load_stage(0);
    for (int c = 0; c < 32; c++) {
        CPWAIT0();
        __syncthreads();
        if (c + 1 < 32) load_stage(c + 1);
        const uint32_t stb = sb + (c & 1)*GSTAGE;
        #pragma unroll
        for (int kk = 0; kk < 2; kk++) {
            uint32_t ah[2][4], al[2][4], bhf[4][2], blf[4][2];
            #pragma unroll
            for (int i = 0; i < 2; i++) {
                int row = 32*wm + 16*i + (l & 15);
                int ko  = kk*16 + ((l >> 4) << 3);
                uint32_t off = (uint32_t)(row*GPITCH + ko*2);
                ldsm4(ah[i][0],ah[i][1],ah[i][2],ah[i][3], stb + 0*GPLANE + off);
                ldsm4(al[i][0],al[i][1],al[i][2],al[i][3], stb + 1*GPLANE + off);
            }
            #pragma unroll
            for (int tp = 0; tp < 2; tp++) {
                int nrow = 32*wn + 16*tp + ((l>>4)<<3) + (l & 7);
                int ko   = kk*16 + (((l>>3)&1) << 3);
                uint32_t off = (uint32_t)(nrow*GPITCH + ko*2);
                ldsm4(bhf[2*tp][0],bhf[2*tp][1],bhf[2*tp+1][0],bhf[2*tp+1][1], stb + 2*GPLANE + off);
                ldsm4(blf[2*tp][0],blf[2*tp][1],blf[2*tp+1][0],blf[2*tp+1][1], stb + 3*GPLANE + off);
            }
            // term-major ordering -> long accumulator reuse distance
            #pragma unroll
            for (int i = 0; i < 2; i++)
                #pragma unroll
                for (int t = 0; t < 4; t++) mma_bf16(acc[i][t], ah[i], bhf[t]);
            #pragma unroll
            for (int i = 0; i < 2; i++)
                #pragma unroll
                for (int t = 0; t < 4; t++) mma_bf16(acc[i][t], ah[i], blf[t]);
            #pragma unroll
            for (int i = 0; i < 2; i++)
                #pragma unroll
                for (int t = 0; t < 4; t++) mma_bf16(acc[i][t], al[i], bhf[t]);
        }
    }

    // epilogue
    if (mode == 1) {
        #pragma unroll
        for (int i = 0; i < 2; i++)
            #pragma unroll
            for (int t = 0; t < 4; t++)
                #pragma unroll
                for (int rr = 0; rr < 2; rr++) {
                    int m = m0 + 32*wm + 16*i + (l>>2) + 8*rr;
                    int n = n0 + 32*wn + 8*t + 2*(l&3);
                    float2 v = make_float2(acc[i][t][2*rr]   + bias[n],
                                           acc[i][t][2*rr+1] + bias[n+1]);
                    *(float2*)&out[(size_t)m*EMBED + n] = v;
                }
    } else {
        __nv_bfloat16* oh = g_qkvh + (size_t)z*MATSZ;
        __nv_bfloat16* ol = g_qkvl + (size_t)z*MATSZ;
        const float scl = (z == 0) ? 0.125f : 1.0f;   // fold 1/sqrt(D) into Q
        #pragma unroll
        for (int i = 0; i < 2; i++)
            #pragma unroll
            for (int t = 0; t < 4; t++)
                #pragma unroll
                for (int rr = 0; rr < 2; rr++) {
                    int m = m0 + 32*wm + 16*i + (l>>2) + 8*rr;
                    int n = n0 + 32*wn + 8*t + 2*(l&3);
                    float v0 = acc[i][t][2*rr]*scl, v1 = acc[i][t][2*rr+1]*scl;
                    uint32_t h = pack2(v0, v1);
                    float h0 = __uint_as_float(h << 16);
                    float h1 = __uint_as_float(h & 0xffff0000u);
                    uint32_t lo = pack2(v0 - h0, v1 - h1);
                    int b = m >> 11, s = m & 2047, hh = n >> 6, d = n & 63;
                    size_t idx = ((((size_t)b*NHEADS + hh)*SEQ) + s)*HDIM + d;
                    *(uint32_t*)(oh + idx) = h;
                    *(uint32_t*)(ol + idx) = lo;
                }
    }
}

// ---------------------------------------------------------------------------
// Flash attention via mma.sync. CTA = 64 q-rows of one (b,h); 4 warps = m16 each.
// 128 threads, 72KB smem (Q streamed through KV buffer 0) -> 3 CTAs/SM.
// K-tiles of 64 keys, 2-stage cp.async. P kept in registers (FA2 style).
// ---------------------------------------------------------------------------
#define APITCH 144
#define AKPL   (64*APITCH)         // 9216
#define ASTAGE (4*AKPL)            // 36864
#define ASMEM  (2*ASTAGE)          // 73728

__global__ __launch_bounds__(128,3) void attn_kernel()
{
    extern __shared__ char sma[];
    const uint32_t sb = s2u(sma);
    const int tid = threadIdx.x, l = tid & 31, wid = tid >> 5;
    const int qt = 31 - (int)blockIdx.x;        // heavy tiles first
    const int bh = blockIdx.y;
    const int q0 = qt * 64;
    const int nkt = qt + 1;
    const size_t base = (size_t)bh * SEQ * HDIM;
    const __nv_bfloat16 *Qh = g_qkvh + base,              *Ql = g_qkvl + base;
    const __nv_bfloat16 *Kh = g_qkvh + MATSZ + base,      *Kl = g_qkvl + MATSZ + base;
    const __nv_bfloat16 *Vh = g_qkvh + 2*(size_t)MATSZ + base,
                        *Vl = g_qkvl + 2*(size_t)MATSZ + base;

    // ---- stream Q planes through stage-0 buffer, extract register frags ----
    #pragma unroll
    for (int i = 0; i < 8; i++) {
        int g = i*128 + tid;
        int p = g >> 9, row = (g >> 3) & 63, ch = g & 7;
        const __nv_bfloat16* src = p ? Ql : Qh;
        cpa16(sb + p*AKPL + row*APITCH + ch*16,
              src + (size_t)(q0 + row)*HDIM + ch*8);
    }
    CPCOMMIT();
    CPWAIT0();
    __syncthreads();

    uint32_t qfh[4][4], qfl[4][4];
    {
        int row = 16*wid + (l & 15);
        #pragma unroll
        for (int kc = 0; kc < 4; kc++) {
            int ko = kc*16 + ((l >> 4) << 3);
            uint32_t off = (uint32_t)(row*APITCH + ko*2);
            ldsm4(qfh[kc][0],qfh[kc][1],qfh[kc][2],qfh[kc][3], sb + 0*AKPL + off);
            ldsm4(qfl[kc][0],qfl[kc][1],qfl[kc][2],qfl[kc][3], sb + 1*AKPL + off);
        }
    }
    __syncthreads();   // all warps done reading Q before buffer 0 is reused

    auto load_kv = [&](int kt){
        const uint32_t stb = sb + (kt & 1)*ASTAGE;
        const int k0 = kt * 64;
        #pragma unroll
        for (int i = 0; i < 16; i++) {
            int g = i*128 + tid;
            int p = g >> 9, row = (g >> 3) & 63, ch = g & 7;  // p: 0 Kh 1 Kl 2 Vh 3 Vl
            const __nv_bfloat16* src = (p==0)?Kh:(p==1)?Kl:(p==2)?Vh:Vl;
            cpa16(stb + p*AKPL + row*APITCH + ch*16,
                  src + (size_t)(k0 + row)*HDIM + ch*8);
        }
        CPCOMMIT();
    };
    load_kv(0);
    CPWAIT0();
    __syncthreads();

    float o[8][4];
    #pragma unroll
    for (int t = 0; t < 8; t++)
        #pragma unroll
        for (int j = 0; j < 4; j++) o[t][j] = 0.f;
    float mr0 = -1e30f, mr1 = -1e30f, lr0 = 0.f, lr1 = 0.f;
    const int qg0 = q0 + 16*wid + (l >> 2);
    const int qg1 = qg0 + 8;

    for (int kt = 0; kt < nkt; kt++) {
        if (kt + 1 < nkt) load_kv(kt + 1);
        const uint32_t stb = sb + (kt & 1)*ASTAGE;
        const int k0 = kt * 64;

        {
            // ---- S = Q K^T (3-term) ----
            float s[8][4];
            #pragma unroll
            for (int t = 0; t < 8; t++)
                #pragma unroll
                for (int j = 0; j < 4; j++) s[t][j] = 0.f;
            #pragma unroll
            for (int kc = 0; kc < 4; kc++) {
                uint32_t bhf[8][2], blf[8][2];
                #pragma unroll
                for (int tp = 0; tp < 4; tp++) {
                    int nrow = 16*tp + ((l>>4)<<3) + (l & 7);
                    int ko   = kc*16 + (((l>>3)&1) << 3);
                    uint32_t off = (uint32_t)(nrow*APITCH + ko*2);
                    ldsm4(bhf[2*tp][0],bhf[2*tp][1],bhf[2*tp+1][0],bhf[2*tp+1][1], stb + 0*AKPL + off);
                    ldsm4(blf[2*tp][0],blf[2*tp][1],blf[2*tp+1][0],blf[2*tp+1][1], stb + 1*AKPL + off);
                }
                #pragma unroll
                for (int t = 0; t < 8; t++) mma_bf16(s[t], qfh[kc], bhf[t]);
                #pragma unroll
                for (int t = 0; t < 8; t++) mma_bf16(s[t], qfh[kc], blf[t]);
                #pragma unroll
                for (int t = 0; t < 8; t++) mma_bf16(s[t], qfl[kc], bhf[t]);
            }
            // ---- causal mask (only near diagonal) ----
            if (k0 + 63 > qg0) {
                #pragma unroll
                for (int t = 0; t < 8; t++) {
                    int kg = k0 + 8*t + 2*(l & 3);
                    if (kg     > qg0) s[t][0] = -1e30f;
                    if (kg + 1 > qg0) s[t][1] = -1e30f;
                    if (kg     > qg1) s[t][2] = -1e30f;
                    if (kg + 1 > qg1) s[t][3] = -1e30f;
                }
            }
            // ---- online softmax (rows qg0, qg1) ----
            float mx0 = -1e30f, mx1 = -1e30f;
            #pragma unroll
            for (int t = 0; t < 8; t++) {
                mx0 = fmaxf(mx0, fmaxf(s[t][0], s[t][1]));
                mx1 = fmaxf(mx1, fmaxf(s[t][2], s[t][3]));
            }
            mx0 = fmaxf(mx0, __shfl_xor_sync(0xffffffffu, mx0, 1));
            mx0 = fmaxf(mx0, __shfl_xor_sync(0xffffffffu, mx0, 2));
            mx1 = fmaxf(mx1, __shfl_xor_sync(0xffffffffu, mx1, 1));
            mx1 = fmaxf(mx1, __shfl_xor_sync(0xffffffffu, mx1, 2));
            float mn0 = fmaxf(mr0, mx0), mn1 = fmaxf(mr1, mx1);
            float a0 = fexp(mr0 - mn0), a1 = fexp(mr1 - mn1);
            mr0 = mn0; mr1 = mn1;
            float rs0 = 0.f, rs1 = 0.f;
            #pragma unroll
            for (int t = 0; t < 8; t++) {
                s[t][0] = fexp(s[t][0] - mn0);
                s[t][1] = fexp(s[t][1] - mn0);
                s[t][2] = fexp(s[t][2] - mn1);
                s[t][3] = fexp(s[t][3] - mn1);
                rs0 += s[t][0] + s[t][1];
                rs1 += s[t][2] + s[t][3];
            }
            rs0 += __shfl_xor_sync(0xffffffffu, rs0, 1);
            rs0 += __shfl_xor_sync(0xffffffffu, rs0, 2);
            rs1 += __shfl_xor_sync(0xffffffffu, rs1, 1);
            rs1 += __shfl_xor_sync(0xffffffffu, rs1, 2);
            lr0 = lr0*a0 + rs0;
            lr1 = lr1*a1 + rs1;
            #pragma unroll
            for (int t = 0; t < 8; t++) {
                o[t][0] *= a0; o[t][1] *= a0; o[t][2] *= a1; o[t][3] *= a1;
            }
            // ---- P -> bf16 hi/lo A-fragments (registers only) ----
            uint32_t ph[4][4], pl[4][4];
            #pragma unroll
            for (int kc = 0; kc < 4; kc++) {
                int t0 = 2*kc, t1 = t0 + 1;
                float pv[4][2] = {{s[t0][0],s[t0][1]},{s[t0][2],s[t0][3]},
                                  {s[t1][0],s[t1][1]},{s[t1][2],s[t1][3]}};
                #pragma unroll
                for (int r = 0; r < 4; r++) {
                    uint32_t h = pack2(pv[r][0], pv[r][1]);
                    float h0 = __uint_as_float(h << 16);
                    float h1 = __uint_as_float(h & 0xffff0000u);
                    ph[kc][r] = h;
                    pl[kc][r] = pack2(pv[r][0] - h0, pv[r][1] - h1);
                }
            }
            // ---- O += P V (3-term), V via ldmatrix.trans ----
            #pragma unroll
            for (int kc = 0; kc < 4; kc++) {
                uint32_t vhf[8][2], vlf[8][2];
                #pragma unroll
                for (int tp = 0; tp < 4; tp++) {
                    int row = kc*16 + ((l>>3)&1)*8 + (l & 7);
                    int co  = 16*tp + ((l >> 4) << 3);
                    uint32_t off = (uint32_t)(row*APITCH + co*2);
                    ldsm4t(vhf[2*tp][0],vhf[2*tp][1],vhf[2*tp+1][0],vhf[2*tp+1][1], stb + 2*AKPL + off);
                    ldsm4t(vlf[2*tp][0],vlf[2*tp][1],vlf[2*tp+1][0],vlf[2*tp+1][1], stb + 3*AKPL + off);
                }
                #pragma unroll
                for (int t = 0; t < 8; t++) mma_bf16(o[t], ph[kc], vhf[t]);
                #pragma unroll
                for (int t = 0; t < 8; t++) mma_bf16(o[t], ph[kc], vlf[t]);
                #pragma unroll
                for (int t = 0; t < 8; t++) mma_bf16(o[t], pl[kc], vhf[t]);
            }
        }
        if (kt + 1 < nkt) { CPWAIT0(); __syncthreads(); }
    }

    // ---- epilogue: normalize, split to bf16 hi/lo, write [B,S,E] planes ----
    const float inv0 = 1.f / lr0, inv1 = 1.f / lr1;
    const int b = bh >> 4, h = bh & 15;
    const int s0 = qg0, s1 = qg1;
    #pragma unroll
    for (int t = 0; t < 8; t++) {
        int d = 8*t + 2*(l & 3);
        int e = h*HDIM + d;
        {
            float v0 = o[t][0]*inv0, v1 = o[t][1]*inv0;
            uint32_t hh = pack2(v0, v1);
            float h0 = __uint_as_float(hh << 16), h1 = __uint_as_float(hh & 0xffff0000u);
            uint32_t ll = pack2(v0 - h0, v1 - h1);
            size_t idx = ((size_t)b*SEQ + s0)*EMBED + e;
            *(uint32_t*)(g_ah + idx) = hh;
            *(uint32_t*)(g_al + idx) = ll;
        }
        {
            float v0 = o[t][2]*inv1, v1 = o[t][3]*inv1;
            uint32_t hh = pack2(v0, v1);
            float h0 = __uint_as_float(hh << 16), h1 = __uint_as_float(hh & 0xffff0000u);
            uint32_t ll = pack2(v0 - h0, v1 - h1);
            size_t idx = ((size_t)b*SEQ + s1)*EMBED + e;
            *(uint32_t*)(g_ah + idx) = hh;
            *(uint32_t*)(g_al + idx) = ll;
        }
    }
}

// ---------------------------------------------------------------------------
extern "C" void kernel_launch(void* const* d_in, const int* in_sizes, int n_in,
                              void* d_out, int out_size)
{
    const float* x  = (const float*)d_in[0];
    const float* Wq = (const float*)d_in[1];
    const float* Wk = (const float*)d_in[2];
    const float* Wv = (const float*)d_in[3];
    const float* Wo = (const float*)d_in[4];
    const float* bo = (const float*)d_in[5];
    float* out = (float*)d_out;

    cudaFuncSetAttribute(gemm_kernel, cudaFuncAttributeMaxDynamicSharedMemorySize, GSMEM);
    cudaFuncSetAttribute(attn_kernel, cudaFuncAttributeMaxDynamicSharedMemorySize, ASMEM);

    splitx_kernel<<<4096, 256>>>(x);
    wprep_kernel<<<dim3(32, 32, 4), dim3(32, 8)>>>(Wq, Wk, Wv, Wo);

    gemm_kernel<<<dim3(8, 32, 3), 512, GSMEM>>>(nullptr, nullptr, 0);  // QKV
    attn_kernel<<<dim3(32, 32), 128, ASMEM>>>();                       // attention
    gemm_kernel<<<dim3(8, 32, 1), 512, GSMEM>>>(out, bo, 1);           // O-proj
}

// round 9
// speedup vs baseline: 1.1227x; 1.0830x over previous
#include <cuda_runtime.h>
#include <cuda_bf16.h>
#include <cstdint>
#include <math.h>

#define BATCH  2
#define SEQ    2048
#define EMBED  1024
#define NHEADS 16
#define HDIM   64
#define MROWS  4096
#define MATSZ  (MROWS*EMBED)     // 4194304
#define WSZ    (EMBED*EMBED)     // 1048576

// ---------------------------------------------------------------------------
// Scratch planes (__device__ globals; allocation-free rule)
// ---------------------------------------------------------------------------
__device__ __nv_bfloat16 g_xh[MATSZ],  g_xl[MATSZ];     // x split      [M,K]
__device__ __nv_bfloat16 g_wh[4*WSZ],  g_wl[4*WSZ];     // W^T split    [N,K] (q,k,v,o)
__device__ __nv_bfloat16 g_qkvh[3*MATSZ], g_qkvl[3*MATSZ]; // q,k,v [B,H,S,D]
__device__ __nv_bfloat16 g_ah[MATSZ],  g_al[MATSZ];     // attn out     [M,E]

// ---------------------------------------------------------------------------
// Helpers
// ---------------------------------------------------------------------------
__device__ __forceinline__ uint32_t s2u(const void* p){
    uint32_t a;
    asm("{ .reg .u64 t; cvta.to.shared.u64 t, %1; cvt.u32.u64 %0, t; }" : "=r"(a) : "l"(p));
    return a;
}
__device__ __forceinline__ uint32_t pack2(float lo, float hi){
    __nv_bfloat162 v = __halves2bfloat162(__float2bfloat16(lo), __float2bfloat16(hi));
    return *reinterpret_cast<uint32_t*>(&v);
}
__device__ __forceinline__ void ldsm4(uint32_t& r0,uint32_t& r1,uint32_t& r2,uint32_t& r3,uint32_t a){
    asm volatile("ldmatrix.sync.aligned.m8n8.x4.shared.b16 {%0,%1,%2,%3}, [%4];"
        : "=r"(r0),"=r"(r1),"=r"(r2),"=r"(r3) : "r"(a));
}
__device__ __forceinline__ void ldsm4t(uint32_t& r0,uint32_t& r1,uint32_t& r2,uint32_t& r3,uint32_t a){
    asm volatile("ldmatrix.sync.aligned.m8n8.x4.trans.shared.b16 {%0,%1,%2,%3}, [%4];"
        : "=r"(r0),"=r"(r1),"=r"(r2),"=r"(r3) : "r"(a));
}
__device__ __forceinline__ void mma_bf16(float* c, const uint32_t* a, const uint32_t* b){
    asm volatile("mma.sync.aligned.m16n8k16.row.col.f32.bf16.bf16.f32 "
        "{%0,%1,%2,%3}, {%4,%5,%6,%7}, {%8,%9}, {%0,%1,%2,%3};"
        : "+f"(c[0]),"+f"(c[1]),"+f"(c[2]),"+f"(c[3])
        : "r"(a[0]),"r"(a[1]),"r"(a[2]),"r"(a[3]), "r"(b[0]),"r"(b[1]));
}
__device__ __forceinline__ void cpa16(uint32_t dst, const void* src){
    asm volatile("cp.async.cg.shared.global [%0], [%1], 16;" :: "r"(dst), "l"(src));
}
#define CPCOMMIT() asm volatile("cp.async.commit_group;" ::: "memory")
#define CPWAIT0()  asm volatile("cp.async.wait_group 0;" ::: "memory")

// FMA-only exp (x <= 0 path): ~3e-6 rel err, no MUFU.
__device__ __forceinline__ float fexp(float x){
    float y = x * 1.4426950408889634f;
    y = fmaxf(y, -126.0f);
    float t = y + 12582912.0f;               // round-to-nearest
    int   n = __float_as_int(t) - 0x4B400000;
    float f = y - (t - 12582912.0f);         // f in [-0.5, 0.5]
    float p = 1.3333558146e-3f;
    p = fmaf(p, f, 9.6181291076e-3f);
    p = fmaf(p, f, 5.5504108665e-2f);
    p = fmaf(p, f, 2.4022650696e-1f);
    p = fmaf(p, f, 6.9314718056e-1f);
    p = fmaf(p, f, 1.0f);
    return __int_as_float(__float_as_int(p) + (n << 23));
}

// ---------------------------------------------------------------------------
// Fused prep: z 0..3 -> transpose+split W (q,k,v,o); z 4..7 -> split x
// block = (32, 8) = 256 threads
// ---------------------------------------------------------------------------
__global__ __launch_bounds__(256) void prep_kernel(
    const float* __restrict__ x,
    const float* __restrict__ Wq, const float* __restrict__ Wk,
    const float* __restrict__ Wv, const float* __restrict__ Wo)
{
    __shared__ float t[32][33];
    const int z = blockIdx.z;
    const int tx = threadIdx.x, ty = threadIdx.y;

    if (z >= 4) {
        // splitx: 4M floats = 1M float4 over 4096 virtual blocks of 256
        int b = (z - 4)*1024 + blockIdx.y*32 + blockIdx.x;
        int i = b*256 + ty*32 + tx;
        float4 v = ((const float4*)x)[i];
        uint32_t h0 = pack2(v.x, v.y), h1 = pack2(v.z, v.w);
        float hx = __uint_as_float(h0 << 16), hy = __uint_as_float(h0 & 0xffff0000u);
        float hz = __uint_as_float(h1 << 16), hw = __uint_as_float(h1 & 0xffff0000u);
        uint32_t l0 = pack2(v.x - hx, v.y - hy), l1 = pack2(v.z - hz, v.w - hw);
        ((uint2*)g_xh)[i] = make_uint2(h0, h1);
        ((uint2*)g_xl)[i] = make_uint2(l0, l1);
        return;
    }

    const float* W = (z==0)?Wq:(z==1)?Wk:(z==2)?Wv:Wo;
    __nv_bfloat16* Oh = g_wh + (size_t)z*WSZ;
    __nv_bfloat16* Ol = g_wl + (size_t)z*WSZ;
    int nb = blockIdx.x*32, kb = blockIdx.y*32;
    #pragma unroll
    for (int r = 0; r < 4; r++)
        t[ty + r*8][tx] = W[(size_t)(kb + ty + r*8)*EMBED + nb + tx];
    __syncthreads();
    #pragma unroll
    for (int r = 0; r < 4; r++) {
        float v = t[tx][ty + r*8];
        __nv_bfloat16 hb = __float2bfloat16(v);
        size_t o = (size_t)(nb + ty + r*8)*EMBED + kb + tx;
        Oh[o] = hb;
        Ol[o] = __float2bfloat16(v - __bfloat162float(hb));
    }
}

// ---------------------------------------------------------------------------
// mma.sync bf16 3-term split GEMM: D[M,N] = A[M,K] @ B^T[N,K]
// CTA 128x128, 512 threads, 16 warps (4m x 4n), warp 32x32, KC=64, 2-stage.
// KC=64: halves barrier count vs KC=32 -> amortizes per-chunk serialization.
// mode 0: A = x planes, B = W_{q,k,v}(z), epilogue -> bf16 hi/lo qkv planes
// mode 1: A = attn planes, B = W_o, epilogue -> fp32 out + bias
// ---------------------------------------------------------------------------
#define GKC 64
#define GNCH (EMBED/GKC)         // 16 chunks
#define GPITCH 144
#define GPLANE (128*GPITCH)      // 18432
#define GSTAGE (4*GPLANE)        // 73728
#define GSMEM  (2*GSTAGE)        // 147456

__global__ __launch_bounds__(512,1) void gemm_kernel(float* __restrict__ out,
                                                     const float* __restrict__ bias,
                                                     int mode)
{
    extern __shared__ char smg[];
    const uint32_t sb = s2u(smg);
    const int tid = threadIdx.x, l = tid & 31, wid = tid >> 5;
    const int wm = wid >> 2, wn = wid & 3;
    const int m0 = blockIdx.y * 128, n0 = blockIdx.x * 128;
    const int z = blockIdx.z;

    const __nv_bfloat16 *Ah, *Al, *Bh, *Bl;
    if (mode == 0) {
        Ah = g_xh; Al = g_xl;
        Bh = g_wh + (size_t)z*WSZ; Bl = g_wl + (size_t)z*WSZ;
    } else {
        Ah = g_ah; Al = g_al;
        Bh = g_wh + 3*(size_t)WSZ; Bl = g_wl + 3*(size_t)WSZ;
    }

    auto load_stage = [&](int c){
        const uint32_t sbase = sb + (c & 1)*GSTAGE;
        const int k0 = c * GKC;
        #pragma unroll
        for (int i = 0; i < 8; i++) {
            int g   = i*512 + tid;        // 0..4095
            int p   = g >> 10;            // 0:Ah 1:Al 2:Bh 3:Bl
            int row = (g >> 3) & 127;
            int ch  = g & 7;
            const __nv_bfloat16* src = (p==0)?Ah:(p==1)?Al:(p==2)?Bh:Bl;
            int grow = (p < 2 ? m0 : n0) + row;
            cpa16(sbase + p*GPLANE + row*GPITCH + ch*16,
                  src + (size_t)grow*EMBED + k0 + ch*8);
        }
        CPCOMMIT();
    };

    float acc[2][4][4];
    #pragma unroll
    for (int i = 0; i < 2; i++)
        #pragma unroll
        for (int t = 0; t < 4; t++)
            #pragma unroll
            for (int j = 0; j < 4; j++) acc[i][t][j] = 0.f;

    load_stage(0);
    for (int c = 0; c < GNCH; c++) {
        CPWAIT0();
        __syncthreads();
        if (c + 1 < GNCH) load_stage(c + 1);
        const uint32_t stb = sb + (c & 1)*GSTAGE;
        #pragma unroll
        for (int kk = 0; kk < 4; kk++) {
            uint32_t ah[2][4], al[2][4], bhf[4][2], blf[4][2];
            #pragma unroll
            for (int i = 0; i < 2; i++) {
                int row = 32*wm + 16*i + (l & 15);
                int ko  = kk*16 + ((l >> 4) << 3);
                uint32_t off = (uint32_t)(row*GPITCH + ko*2);
                ldsm4(ah[i][0],ah[i][1],ah[i][2],ah[i][3], stb + 0*GPLANE + off);
                ldsm4(al[i][0],al[i][1],al[i][2],al[i][3], stb + 1*GPLANE + off);
            }
            #pragma unroll
            for (int tp = 0; tp < 2; tp++) {
                int nrow = 32*wn + 16*tp + ((l>>4)<<3) + (l & 7);
                int ko   = kk*16 + (((l>>3)&1) << 3);
                uint32_t off = (uint32_t)(nrow*GPITCH + ko*2);
                ldsm4(bhf[2*tp][0],bhf[2*tp][1],bhf[2*tp+1][0],bhf[2*tp+1][1], stb + 2*GPLANE + off);
                ldsm4(blf[2*tp][0],blf[2*tp][1],blf[2*tp+1][0],blf[2*tp+1][1], stb + 3*GPLANE + off);
            }
            // term-major ordering -> long accumulator reuse distance
            #pragma unroll
            for (int i = 0; i < 2; i++)
                #pragma unroll
                for (int t = 0; t < 4; t++) mma_bf16(acc[i][t], ah[i], bhf[t]);
            #pragma unroll
            for (int i = 0; i < 2; i++)
                #pragma unroll
                for (int t = 0; t < 4; t++) mma_bf16(acc[i][t], ah[i], blf[t]);
            #pragma unroll
            for (int i = 0; i < 2; i++)
                #pragma unroll
                for (int t = 0; t < 4; t++) mma_bf16(acc[i][t], al[i], bhf[t]);
        }
    }

    // epilogue
    if (mode == 1) {
        #pragma unroll
        for (int i = 0; i < 2; i++)
            #pragma unroll
            for (int t = 0; t < 4; t++)
                #pragma unroll
                for (int rr = 0; rr < 2; rr++) {
                    int m = m0 + 32*wm + 16*i + (l>>2) + 8*rr;
                    int n = n0 + 32*wn + 8*t + 2*(l&3);
                    float2 v = make_float2(acc[i][t][2*rr]   + bias[n],
                                           acc[i][t][2*rr+1] + bias[n+1]);
                    *(float2*)&out[(size_t)m*EMBED + n] = v;
                }
    } else {
        __nv_bfloat16* oh = g_qkvh + (size_t)z*MATSZ;
        __nv_bfloat16* ol = g_qkvl + (size_t)z*MATSZ;
        const float scl = (z == 0) ? 0.125f : 1.0f;   // fold 1/sqrt(D) into Q
        #pragma unroll
        for (int i = 0; i < 2; i++)
            #pragma unroll
            for (int t = 0; t < 4; t++)
                #pragma unroll
                for (int rr = 0; rr < 2; rr++) {
                    int m = m0 + 32*wm + 16*i + (l>>2) + 8*rr;
                    int n = n0 + 32*wn + 8*t + 2*(l&3);
                    float v0 = acc[i][t][2*rr]*scl, v1 = acc[i][t][2*rr+1]*scl;
                    uint32_t h = pack2(v0, v1);
                    float h0 = __uint_as_float(h << 16);
                    float h1 = __uint_as_float(h & 0xffff0000u);
                    uint32_t lo = pack2(v0 - h0, v1 - h1);
                    int b = m >> 11, s = m & 2047, hh = n >> 6, d = n & 63;
                    size_t idx = ((((size_t)b*NHEADS + hh)*SEQ) + s)*HDIM + d;
                    *(uint32_t*)(oh + idx) = h;
                    *(uint32_t*)(ol + idx) = lo;
                }
    }
}

// ---------------------------------------------------------------------------
// Flash attention via mma.sync. CTA = 64 q-rows of one (b,h); 4 warps = m16 each.
// 128 threads, 72KB smem (Q streamed through KV buffer 0) -> 3 CTAs/SM.
// K-tiles of 64 keys, 2-stage cp.async. P kept in registers (FA2 style).
// ---------------------------------------------------------------------------
#define APITCH 144
#define AKPL   (64*APITCH)         // 9216
#define ASTAGE (4*AKPL)            // 36864
#define ASMEM  (2*ASTAGE)          // 73728

__global__ __launch_bounds__(128,3) void attn_kernel()
{
    extern __shared__ char sma[];
    const uint32_t sb = s2u(sma);
    const int tid = threadIdx.x, l = tid & 31, wid = tid >> 5;
    const int qt = 31 - (int)blockIdx.x;        // heavy tiles first
    const int bh = blockIdx.y;
    const int q0 = qt * 64;
    const int nkt = qt + 1;
    const size_t base = (size_t)bh * SEQ * HDIM;
    const __nv_bfloat16 *Qh = g_qkvh + base,              *Ql = g_qkvl + base;
    const __nv_bfloat16 *Kh = g_qkvh + MATSZ + base,      *Kl = g_qkvl + MATSZ + base;
    const __nv_bfloat16 *Vh = g_qkvh + 2*(size_t)MATSZ + base,
                        *Vl = g_qkvl + 2*(size_t)MATSZ + base;

    // ---- stream Q planes through stage-0 buffer, extract register frags ----
    #pragma unroll
    for (int i = 0; i < 8; i++) {
        int g = i*128 + tid;
        int p = g >> 9, row = (g >> 3) & 63, ch = g & 7;
        const __nv_bfloat16* src = p ? Ql : Qh;
        cpa16(sb + p*AKPL + row*APITCH + ch*16,
              src + (size_t)(q0 + row)*HDIM + ch*8);
    }
    CPCOMMIT();
    CPWAIT0();
    __syncthreads();

    uint32_t qfh[4][4], qfl[4][4];
    {
        int row = 16*wid + (l & 15);
        #pragma unroll
        for (int kc = 0; kc < 4; kc++) {
            int ko = kc*16 + ((l >> 4) << 3);
            uint32_t off = (uint32_t)(row*APITCH + ko*2);
            ldsm4(qfh[kc][0],qfh[kc][1],qfh[kc][2],qfh[kc][3], sb + 0*AKPL + off);
            ldsm4(qfl[kc][0],qfl[kc][1],qfl[kc][2],qfl[kc][3], sb + 1*AKPL + off);
        }
    }
    __syncthreads();   // all warps done reading Q before buffer 0 is reused

    auto load_kv = [&](int kt){
        const uint32_t stb = sb + (kt & 1)*ASTAGE;
        const int k0 = kt * 64;
        #pragma unroll
        for (int i = 0; i < 16; i++) {
            int g = i*128 + tid;
            int p = g >> 9, row = (g >> 3) & 63, ch = g & 7;  // p: 0 Kh 1 Kl 2 Vh 3 Vl
            const __nv_bfloat16* src = (p==0)?Kh:(p==1)?Kl:(p==2)?Vh:Vl;
            cpa16(stb + p*AKPL + row*APITCH + ch*16,
                  src + (size_t)(k0 + row)*HDIM + ch*8);
        }
        CPCOMMIT();
    };
    load_kv(0);
    CPWAIT0();
    __syncthreads();

    float o[8][4];
    #pragma unroll
    for (int t = 0; t < 8; t++)
        #pragma unroll
        for (int j = 0; j < 4; j++) o[t][j] = 0.f;
    float mr0 = -1e30f, mr1 = -1e30f, lr0 = 0.f, lr1 = 0.f;
    const int qg0 = q0 + 16*wid + (l >> 2);
    const int qg1 = qg0 + 8;

    for (int kt = 0; kt < nkt; kt++) {
        if (kt + 1 < nkt) load_kv(kt + 1);
        const uint32_t stb = sb + (kt & 1)*ASTAGE;
        const int k0 = kt * 64;

        {
            // ---- S = Q K^T (3-term) ----
            float s[8][4];
            #pragma unroll
            for (int t = 0; t < 8; t++)
                #pragma unroll
                for (int j = 0; j < 4; j++) s[t][j] = 0.f;
            #pragma unroll
            for (int kc = 0; kc < 4; kc++) {
                uint32_t bhf[8][2], blf[8][2];
                #pragma unroll
                for (int tp = 0; tp < 4; tp++) {
                    int nrow = 16*tp + ((l>>4)<<3) + (l & 7);
                    int ko   = kc*16 + (((l>>3)&1) << 3);
                    uint32_t off = (uint32_t)(nrow*APITCH + ko*2);
                    ldsm4(bhf[2*tp][0],bhf[2*tp][1],bhf[2*tp+1][0],bhf[2*tp+1][1], stb + 0*AKPL + off);
                    ldsm4(blf[2*tp][0],blf[2*tp][1],blf[2*tp+1][0],blf[2*tp+1][1], stb + 1*AKPL + off);
                }
                #pragma unroll
                for (int t = 0; t < 8; t++) mma_bf16(s[t], qfh[kc], bhf[t]);
                #pragma unroll
                for (int t = 0; t < 8; t++) mma_bf16(s[t], qfh[kc], blf[t]);
                #pragma unroll
                for (int t = 0; t < 8; t++) mma_bf16(s[t], qfl[kc], bhf[t]);
            }
            // ---- causal mask (only near diagonal) ----
            if (k0 + 63 > qg0) {
                #pragma unroll
                for (int t = 0; t < 8; t++) {
                    int kg = k0 + 8*t + 2*(l & 3);
                    if (kg     > qg0) s[t][0] = -1e30f;
                    if (kg + 1 > qg0) s[t][1] = -1e30f;
                    if (kg     > qg1) s[t][2] = -1e30f;
                    if (kg + 1 > qg1) s[t][3] = -1e30f;
                }
            }
            // ---- online softmax (rows qg0, qg1) ----
            float mx0 = -1e30f, mx1 = -1e30f;
            #pragma unroll
            for (int t = 0; t < 8; t++) {
                mx0 = fmaxf(mx0, fmaxf(s[t][0], s[t][1]));
                mx1 = fmaxf(mx1, fmaxf(s[t][2], s[t][3]));
            }
            mx0 = fmaxf(mx0, __shfl_xor_sync(0xffffffffu, mx0, 1));
            mx0 = fmaxf(mx0, __shfl_xor_sync(0xffffffffu, mx0, 2));
            mx1 = fmaxf(mx1, __shfl_xor_sync(0xffffffffu, mx1, 1));
            mx1 = fmaxf(mx1, __shfl_xor_sync(0xffffffffu, mx1, 2));
            float mn0 = fmaxf(mr0, mx0), mn1 = fmaxf(mr1, mx1);
            float a0 = fexp(mr0 - mn0), a1 = fexp(mr1 - mn1);
            mr0 = mn0; mr1 = mn1;
            float rs0 = 0.f, rs1 = 0.f;
            #pragma unroll
            for (int t = 0; t < 8; t++) {
                s[t][0] = fexp(s[t][0] - mn0);
                s[t][1] = fexp(s[t][1] - mn0);
                s[t][2] = fexp(s[t][2] - mn1);
                s[t][3] = fexp(s[t][3] - mn1);
                rs0 += s[t][0] + s[t][1];
                rs1 += s[t][2] + s[t][3];
            }
            rs0 += __shfl_xor_sync(0xffffffffu, rs0, 1);
            rs0 += __shfl_xor_sync(0xffffffffu, rs0, 2);
            rs1 += __shfl_xor_sync(0xffffffffu, rs1, 1);
            rs1 += __shfl_xor_sync(0xffffffffu, rs1, 2);
            lr0 = lr0*a0 + rs0;
            lr1 = lr1*a1 + rs1;
            #pragma unroll
            for (int t = 0; t < 8; t++) {
                o[t][0] *= a0; o[t][1] *= a0; o[t][2] *= a1; o[t][3] *= a1;
            }
            // ---- P -> bf16 hi/lo A-fragments (registers only) ----
            uint32_t ph[4][4], pl[4][4];
            #pragma unroll
            for (int kc = 0; kc < 4; kc++) {
                int t0 = 2*kc, t1 = t0 + 1;
                float pv[4][2] = {{s[t0][0],s[t0][1]},{s[t0][2],s[t0][3]},
                                  {s[t1][0],s[t1][1]},{s[t1][2],s[t1][3]}};
                #pragma unroll
                for (int r = 0; r < 4; r++) {
                    uint32_t h = pack2(pv[r][0], pv[r][1]);
                    float h0 = __uint_as_float(h << 16);
                    float h1 = __uint_as_float(h & 0xffff0000u);
                    ph[kc][r] = h;
                    pl[kc][r] = pack2(pv[r][0] - h0, pv[r][1] - h1);
                }
            }
            // ---- O += P V (3-term), V via ldmatrix.trans ----
            #pragma unroll
            for (int kc = 0; kc < 4; kc++) {
                uint32_t vhf[8][2], vlf[8][2];
                #pragma unroll
                for (int tp = 0; tp < 4; tp++) {
                    int row = kc*16 + ((l>>3)&1)*8 + (l & 7);
                    int co  = 16*tp + ((l >> 4) << 3);
                    uint32_t off = (uint32_t)(row*APITCH + co*2);
                    ldsm4t(vhf[2*tp][0],vhf[2*tp][1],vhf[2*tp+1][0],vhf[2*tp+1][1], stb + 2*AKPL + off);
                    ldsm4t(vlf[2*tp][0],vlf[2*tp][1],vlf[2*tp+1][0],vlf[2*tp+1][1], stb + 3*AKPL + off);
                }
                #pragma unroll
                for (int t = 0; t < 8; t++) mma_bf16(o[t], ph[kc], vhf[t]);
                #pragma unroll
                for (int t = 0; t < 8; t++) mma_bf16(o[t], ph[kc], vlf[t]);
                #pragma unroll
                for (int t = 0; t < 8; t++) mma_bf16(o[t], pl[kc], vhf[t]);
            }
        }
        if (kt + 1 < nkt) { CPWAIT0(); __syncthreads(); }
    }

    // ---- epilogue: normalize, split to bf16 hi/lo, write [B,S,E] planes ----
    const float inv0 = 1.f / lr0, inv1 = 1.f / lr1;
    const int b = bh >> 4, h = bh & 15;
    const int s0 = qg0, s1 = qg1;
    #pragma unroll
    for (int t = 0; t < 8; t++) {
        int d = 8*t + 2*(l & 3);
        int e = h*HDIM + d;
        {
            float v0 = o[t][0]*inv0, v1 = o[t][1]*inv0;
            uint32_t hh = pack2(v0, v1);
            float h0 = __uint_as_float(hh << 16), h1 = __uint_as_float(hh & 0xffff0000u);
            uint32_t ll = pack2(v0 - h0, v1 - h1);
            size_t idx = ((size_t)b*SEQ + s0)*EMBED + e;
            *(uint32_t*)(g_ah + idx) = hh;
            *(uint32_t*)(g_al + idx) = ll;
        }
        {
            float v0 = o[t][2]*inv1, v1 = o[t][3]*inv1;
            uint32_t hh = pack2(v0, v1);
            float h0 = __uint_as_float(hh << 16), h1 = __uint_as_float(hh & 0xffff0000u);
            uint32_t ll = pack2(v0 - h0, v1 - h1);
            size_t idx = ((size_t)b*SEQ + s1)*EMBED + e;
            *(uint32_t*)(g_ah + idx) = hh;
            *(uint32_t*)(g_al + idx) = ll;
        }
    }
}

// ---------------------------------------------------------------------------
extern "C" void kernel_launch(void* const* d_in, const int* in_sizes, int n_in,
                              void* d_out, int out_size)
{
    const float* x  = (const float*)d_in[0];
    const float* Wq = (const float*)d_in[1];
    const float* Wk = (const float*)d_in[2];
    const float* Wv = (const float*)d_in[3];
    const float* Wo = (const float*)d_in[4];
    const float* bo = (const float*)d_in[5];
    float* out = (float*)d_out;

    cudaFuncSetAttribute(gemm_kernel, cudaFuncAttributeMaxDynamicSharedMemorySize, GSMEM);
    cudaFuncSetAttribute(attn_kernel, cudaFuncAttributeMaxDynamicSharedMemorySize, ASMEM);

    prep_kernel<<<dim3(32, 32, 8), dim3(32, 8)>>>(x, Wq, Wk, Wv, Wo);

    gemm_kernel<<<dim3(8, 32, 3), 512, GSMEM>>>(nullptr, nullptr, 0);  // QKV
    attn_kernel<<<dim3(32, 32), 128, ASMEM>>>();                       // attention
    gemm_kernel<<<dim3(8, 32, 1), 512, GSMEM>>>(out, bo, 1);           // O-proj
}

// round 11
// speedup vs baseline: 1.1605x; 1.0336x over previous
#include <cuda_runtime.h>
#include <cuda_bf16.h>
#include <cstdint>
#include <math.h>

#define BATCH  2
#define SEQ    2048
#define EMBED  1024
#define NHEADS 16
#define HDIM   64
#define MROWS  4096
#define MATSZ  (MROWS*EMBED)     // 4194304
#define WSZ    (EMBED*EMBED)     // 1048576

// ---------------------------------------------------------------------------
// Scratch planes (__device__ globals; allocation-free rule)
// ---------------------------------------------------------------------------
__device__ __nv_bfloat16 g_xh[MATSZ],  g_xl[MATSZ];     // x split      [M,K]
__device__ __nv_bfloat16 g_wh[4*WSZ],  g_wl[4*WSZ];     // W^T split    [N,K] (q,k,v,o)
__device__ __nv_bfloat16 g_qkvh[3*MATSZ], g_qkvl[3*MATSZ]; // q,k,v [B,H,S,D]
__device__ __nv_bfloat16 g_ah[MATSZ],  g_al[MATSZ];     // attn out     [M,E]

// ---------------------------------------------------------------------------
// Helpers
// ---------------------------------------------------------------------------
__device__ __forceinline__ uint32_t s2u(const void* p){
    uint32_t a;
    asm("{ .reg .u64 t; cvta.to.shared.u64 t, %1; cvt.u32.u64 %0, t; }" : "=r"(a) : "l"(p));
    return a;
}
__device__ __forceinline__ uint32_t pack2(float lo, float hi){
    __nv_bfloat162 v = __halves2bfloat162(__float2bfloat16(lo), __float2bfloat16(hi));
    return *reinterpret_cast<uint32_t*>(&v);
}
__device__ __forceinline__ void ldsm4(uint32_t& r0,uint32_t& r1,uint32_t& r2,uint32_t& r3,uint32_t a){
    asm volatile("ldmatrix.sync.aligned.m8n8.x4.shared.b16 {%0,%1,%2,%3}, [%4];"
        : "=r"(r0),"=r"(r1),"=r"(r2),"=r"(r3) : "r"(a));
}
__device__ __forceinline__ void ldsm4t(uint32_t& r0,uint32_t& r1,uint32_t& r2,uint32_t& r3,uint32_t a){
    asm volatile("ldmatrix.sync.aligned.m8n8.x4.trans.shared.b16 {%0,%1,%2,%3}, [%4];"
        : "=r"(r0),"=r"(r1),"=r"(r2),"=r"(r3) : "r"(a));
}
__device__ __forceinline__ void mma_bf16(float* c, const uint32_t* a, const uint32_t* b){
    asm volatile("mma.sync.aligned.m16n8k16.row.col.f32.bf16.bf16.f32 "
        "{%0,%1,%2,%3}, {%4,%5,%6,%7}, {%8,%9}, {%0,%1,%2,%3};"
        : "+f"(c[0]),"+f"(c[1]),"+f"(c[2]),"+f"(c[3])
        : "r"(a[0]),"r"(a[1]),"r"(a[2]),"r"(a[3]), "r"(b[0]),"r"(b[1]));
}
__device__ __forceinline__ void cpa16(uint32_t dst, const void* src){
    asm volatile("cp.async.cg.shared.global [%0], [%1], 16;" :: "r"(dst), "l"(src));
}
#define CPCOMMIT() asm volatile("cp.async.commit_group;" ::: "memory")
#define CPWAIT0()  asm volatile("cp.async.wait_group 0;" ::: "memory")

// FMA-only exp (x <= 0 path): ~3e-6 rel err, no MUFU.
__device__ __forceinline__ float fexp(float x){
    float y = x * 1.4426950408889634f;
    y = fmaxf(y, -126.0f);
    float t = y + 12582912.0f;               // round-to-nearest
    int   n = __float_as_int(t) - 0x4B400000;
    float f = y - (t - 12582912.0f);         // f in [-0.5, 0.5]
    float p = 1.3333558146e-3f;
    p = fmaf(p, f, 9.6181291076e-3f);
    p = fmaf(p, f, 5.5504108665e-2f);
    p = fmaf(p, f, 2.4022650696e-1f);
    p = fmaf(p, f, 6.9314718056e-1f);
    p = fmaf(p, f, 1.0f);
    return __int_as_float(__float_as_int(p) + (n << 23));
}

// ---------------------------------------------------------------------------
// Fused prep: z 0..3 -> transpose+split W (q,k,v,o); z 4..7 -> split x
// block = (32, 8) = 256 threads
// ---------------------------------------------------------------------------
__global__ __launch_bounds__(256) void prep_kernel(
    const float* __restrict__ x,
    const float* __restrict__ Wq, const float* __restrict__ Wk,
    const float* __restrict__ Wv, const float* __restrict__ Wo)
{
    __shared__ float t[32][33];
    const int z = blockIdx.z;
    const int tx = threadIdx.x, ty = threadIdx.y;

    if (z >= 4) {
        int b = (z - 4)*1024 + blockIdx.y*32 + blockIdx.x;
        int i = b*256 + ty*32 + tx;
        float4 v = ((const float4*)x)[i];
        uint32_t h0 = pack2(v.x, v.y), h1 = pack2(v.z, v.w);
        float hx = __uint_as_float(h0 << 16), hy = __uint_as_float(h0 & 0xffff0000u);
        float hz = __uint_as_float(h1 << 16), hw = __uint_as_float(h1 & 0xffff0000u);
        uint32_t l0 = pack2(v.x - hx, v.y - hy), l1 = pack2(v.z - hz, v.w - hw);
        ((uint2*)g_xh)[i] = make_uint2(h0, h1);
        ((uint2*)g_xl)[i] = make_uint2(l0, l1);
        return;
    }

    const float* W = (z==0)?Wq:(z==1)?Wk:(z==2)?Wv:Wo;
    __nv_bfloat16* Oh = g_wh + (size_t)z*WSZ;
    __nv_bfloat16* Ol = g_wl + (size_t)z*WSZ;
    int nb = blockIdx.x*32, kb = blockIdx.y*32;
    #pragma unroll
    for (int r = 0; r < 4; r++)
        t[ty + r*8][tx] = W[(size_t)(kb + ty + r*8)*EMBED + nb + tx];
    __syncthreads();
    #pragma unroll
    for (int r = 0; r < 4; r++) {
        float v = t[tx][ty + r*8];
        __nv_bfloat16 hb = __float2bfloat16(v);
        size_t o = (size_t)(nb + ty + r*8)*EMBED + kb + tx;
        Oh[o] = hb;
        Ol[o] = __float2bfloat16(v - __bfloat162float(hb));
    }
}

// ---------------------------------------------------------------------------
// mma.sync bf16 3-term split GEMM: D[M,N] = A[M,K] @ B^T[N,K]
// CTA 128x256, 512 threads, 16 warps (4m x 4n), warp 32x64, KC=32, 2-stage.
// Wider warp tile: 128 B smem traffic per MMA (was 171) -> tests smem-BW bound.
// B hi/lo fragments loaded sequentially into one buffer to stay <=128 regs.
// mode 0: A = x planes, B = W_{q,k,v}(z), epilogue -> bf16 hi/lo qkv planes
// mode 1: A = attn planes, B = W_o, epilogue -> fp32 out + bias
// ---------------------------------------------------------------------------
#define GKC 32
#define GNCH (EMBED/GKC)         // 32 chunks
#define GPITCH 80
#define GAPL  (128*GPITCH)       // 10240 (A plane)
#define GBPL  (256*GPITCH)       // 20480 (B plane)
#define GB_OFF (2*GAPL)          // 20480 (B region start)
#define GSTAGE (2*GAPL + 2*GBPL) // 61440
#define GSMEM  (2*GSTAGE)        // 122880

__global__ __launch_bounds__(512,1) void gemm_kernel(float* __restrict__ out,
                                                     const float* __restrict__ bias,
                                                     int mode)
{
    extern __shared__ char smg[];
    const uint32_t sb = s2u(smg);
    const int tid = threadIdx.x, l = tid & 31, wid = tid >> 5;
    const int wm = wid >> 2, wn = wid & 3;
    const int m0 = blockIdx.y * 128, n0 = blockIdx.x * 256;
    const int z = blockIdx.z;

    const __nv_bfloat16 *Ah, *Al, *Bh, *Bl;
    if (mode == 0) {
        Ah = g_xh; Al = g_xl;
        Bh = g_wh + (size_t)z*WSZ; Bl = g_wl + (size_t)z*WSZ;
    } else {
        Ah = g_ah; Al = g_al;
        Bh = g_wh + 3*(size_t)WSZ; Bl = g_wl + 3*(size_t)WSZ;
    }

    // 3072 float4 per stage over 512 threads: A region then B region
    auto load_stage = [&](int c){
        const uint32_t sbase = sb + (c & 1)*GSTAGE;
        const int k0 = c * GKC;
        #pragma unroll
        for (int i = 0; i < 2; i++) {        // A: 2 planes x 128 rows x 4 ch
            int g   = i*512 + tid;
            int p   = g >> 9;
            int row = (g >> 2) & 127;
            int ch  = g & 3;
            const __nv_bfloat16* src = p ? Al : Ah;
            cpa16(sbase + p*GAPL + row*GPITCH + ch*16,
                  src + (size_t)(m0 + row)*EMBED + k0 + ch*8);
        }
        #pragma unroll
        for (int i = 0; i < 4; i++) {        // B: 2 planes x 256 rows x 4 ch
            int g   = i*512 + tid;
            int p   = g >> 10;
            int row = (g >> 2) & 255;
            int ch  = g & 3;
            const __nv_bfloat16* src = p ? Bl : Bh;
            cpa16(sbase + GB_OFF + p*GBPL + row*GPITCH + ch*16,
                  src + (size_t)(n0 + row)*EMBED + k0 + ch*8);
        }
        CPCOMMIT();
    };

    float acc[2][8][4];
    #pragma unroll
    for (int i = 0; i < 2; i++)
        #pragma unroll
        for (int t = 0; t < 8; t++)
            #pragma unroll
            for (int j = 0; j < 4; j++) acc[i][t][j] = 0.f;

    load_stage(0);
    for (int c = 0; c < GNCH; c++) {
        CPWAIT0();
        __syncthreads();
        if (c + 1 < GNCH) load_stage(c + 1);
        const uint32_t stb = sb + (c & 1)*GSTAGE;
        #pragma unroll
        for (int kk = 0; kk < 2; kk++) {
            uint32_t ah[2][4], al[2][4], bf[8][2];
            #pragma unroll
            for (int i = 0; i < 2; i++) {
                int row = 32*wm + 16*i + (l & 15);
                int ko  = kk*16 + ((l >> 4) << 3);
                uint32_t off = (uint32_t)(row*GPITCH + ko*2);
                ldsm4(ah[i][0],ah[i][1],ah[i][2],ah[i][3], stb + 0*GAPL + off);
                ldsm4(al[i][0],al[i][1],al[i][2],al[i][3], stb + 1*GAPL + off);
            }
            {   // B-hi fragments
                #pragma unroll
                for (int tp = 0; tp < 4; tp++) {
                    int nrow = 64*wn + 16*tp + ((l>>4)<<3) + (l & 7);
                    int ko   = kk*16 + (((l>>3)&1) << 3);
                    uint32_t off = (uint32_t)(nrow*GPITCH + ko*2);
                    ldsm4(bf[2*tp][0],bf[2*tp][1],bf[2*tp+1][0],bf[2*tp+1][1],
                          stb + GB_OFF + 0*GBPL + off);
                }
                #pragma unroll
                for (int i = 0; i < 2; i++)
                    #pragma unroll
                    for (int t = 0; t < 8; t++) mma_bf16(acc[i][t], ah[i], bf[t]);
                #pragma unroll
                for (int i = 0; i < 2; i++)
                    #pragma unroll
                    for (int t = 0; t < 8; t++) mma_bf16(acc[i][t], al[i], bf[t]);
            }
            {   // B-lo fragments (reuse buffer)
                #pragma unroll
                for (int tp = 0; tp < 4; tp++) {
                    int nrow = 64*wn + 16*tp + ((l>>4)<<3) + (l & 7);
                    int ko   = kk*16 + (((l>>3)&1) << 3);
                    uint32_t off = (uint32_t)(nrow*GPITCH + ko*2);
                    ldsm4(bf[2*tp][0],bf[2*tp][1],bf[2*tp+1][0],bf[2*tp+1][1],
                          stb + GB_OFF + 1*GBPL + off);
                }
                #pragma unroll
                for (int i = 0; i < 2; i++)
                    #pragma unroll
                    for (int t = 0; t < 8; t++) mma_bf16(acc[i][t], ah[i], bf[t]);
            }
        }
    }

    // epilogue
    if (mode == 1) {
        #pragma unroll
        for (int i = 0; i < 2; i++)
            #pragma unroll
            for (int t = 0; t < 8; t++)
                #pragma unroll
                for (int rr = 0; rr < 2; rr++) {
                    int m = m0 + 32*wm + 16*i + (l>>2) + 8*rr;
                    int n = n0 + 64*wn + 8*t + 2*(l&3);
                    float2 v = make_float2(acc[i][t][2*rr]   + bias[n],
                                           acc[i][t][2*rr+1] + bias[n+1]);
                    *(float2*)&out[(size_t)m*EMBED + n] = v;
                }
    } else {
        __nv_bfloat16* oh = g_qkvh + (size_t)z*MATSZ;
        __nv_bfloat16* ol = g_qkvl + (size_t)z*MATSZ;
        const float scl = (z == 0) ? 0.125f : 1.0f;   // fold 1/sqrt(D) into Q
        #pragma unroll
        for (int i = 0; i < 2; i++)
            #pragma unroll
            for (int t = 0; t < 8; t++)
                #pragma unroll
                for (int rr = 0; rr < 2; rr++) {
                    int m = m0 + 32*wm + 16*i + (l>>2) + 8*rr;
                    int n = n0 + 64*wn + 8*t + 2*(l&3);
                    float v0 = acc[i][t][2*rr]*scl, v1 = acc[i][t][2*rr+1]*scl;
                    uint32_t h = pack2(v0, v1);
                    float h0 = __uint_as_float(h << 16);
                    float h1 = __uint_as_float(h & 0xffff0000u);
                    uint32_t lo = pack2(v0 - h0, v1 - h1);
                    int b = m >> 11, s = m & 2047, hh = n >> 6, d = n & 63;
                    size_t idx = ((((size_t)b*NHEADS + hh)*SEQ) + s)*HDIM + d;
                    *(uint32_t*)(oh + idx) = h;
                    *(uint32_t*)(ol + idx) = lo;
                }
    }
}

// ---------------------------------------------------------------------------
// Flash attention via mma.sync. CTA = 64 q-rows of one (b,h); 4 warps = m16 each.
// 128 threads, 72KB smem (Q streamed through KV buffer 0) -> 3 CTAs/SM.
// K-tiles of 64 keys, 2-stage cp.async. P kept in registers (FA2 style).
// ---------------------------------------------------------------------------
#define APITCH 144
#define AKPL   (64*APITCH)         // 9216
#define ASTAGE (4*AKPL)            // 36864
#define ASMEM  (2*ASTAGE)          // 73728

__global__ __launch_bounds__(128,3) void attn_kernel()
{
    extern __shared__ char sma[];
    const uint32_t sb = s2u(sma);
    const int tid = threadIdx.x, l = tid & 31, wid = tid >> 5;
    const int qt = 31 - (int)blockIdx.x;        // heavy tiles first
    const int bh = blockIdx.y;
    const int q0 = qt * 64;
    const int nkt = qt + 1;
    const size_t base = (size_t)bh * SEQ * HDIM;
    const __nv_bfloat16 *Qh = g_qkvh + base,              *Ql = g_qkvl + base;
    const __nv_bfloat16 *Kh = g_qkvh + MATSZ + base,      *Kl = g_qkvl + MATSZ + base;
    const __nv_bfloat16 *Vh = g_qkvh + 2*(size_t)MATSZ + base,
                        *Vl = g_qkvl + 2*(size_t)MATSZ + base;

    // ---- stream Q planes through stage-0 buffer, extract register frags ----
    #pragma unroll
    for (int i = 0; i < 8; i++) {
        int g = i*128 + tid;
        int p = g >> 9, row = (g >> 3) & 63, ch = g & 7;
        const __nv_bfloat16* src = p ? Ql : Qh;
        cpa16(sb + p*AKPL + row*APITCH + ch*16,
              src + (size_t)(q0 + row)*HDIM + ch*8);
    }
    CPCOMMIT();
    CPWAIT0();
    __syncthreads();

    uint32_t qfh[4][4], qfl[4][4];
    {
        int row = 16*wid + (l & 15);
        #pragma unroll
        for (int kc = 0; kc < 4; kc++) {
            int ko = kc*16 + ((l >> 4) << 3);
            uint32_t off = (uint32_t)(row*APITCH + ko*2);
            ldsm4(qfh[kc][0],qfh[kc][1],qfh[kc][2],qfh[kc][3], sb + 0*AKPL + off);
            ldsm4(qfl[kc][0],qfl[kc][1],qfl[kc][2],qfl[kc][3], sb + 1*AKPL + off);
        }
    }
    __syncthreads();   // all warps done reading Q before buffer 0 is reused

    auto load_kv = [&](int kt){
        const uint32_t stb = sb + (kt & 1)*ASTAGE;
        const int k0 = kt * 64;
        #pragma unroll
        for (int i = 0; i < 16; i++) {
            int g = i*128 + tid;
            int p = g >> 9, row = (g >> 3) & 63, ch = g & 7;  // p: 0 Kh 1 Kl 2 Vh 3 Vl
            const __nv_bfloat16* src = (p==0)?Kh:(p==1)?Kl:(p==2)?Vh:Vl;
            cpa16(stb + p*AKPL + row*APITCH + ch*16,
                  src + (size_t)(k0 + row)*HDIM + ch*8);
        }
        CPCOMMIT();
    };
    load_kv(0);
    CPWAIT0();
    __syncthreads();

    float o[8][4];
    #pragma unroll
    for (int t = 0; t < 8; t++)
        #pragma unroll
        for (int j = 0; j < 4; j++) o[t][j] = 0.f;
    float mr0 = -1e30f, mr1 = -1e30f, lr0 = 0.f, lr1 = 0.f;
    const int qg0 = q0 + 16*wid + (l >> 2);
    const int qg1 = qg0 + 8;

    for (int kt = 0; kt < nkt; kt++) {
        if (kt + 1 < nkt) load_kv(kt + 1);
        const uint32_t stb = sb + (kt & 1)*ASTAGE;
        const int k0 = kt * 64;

        {
            // ---- S = Q K^T (3-term) ----
            float s[8][4];
            #pragma unroll
            for (int t = 0; t < 8; t++)
                #pragma unroll
                for (int j = 0; j < 4; j++) s[t][j] = 0.f;
            #pragma unroll
            for (int kc = 0; kc < 4; kc++) {
                uint32_t bhf[8][2], blf[8][2];
                #pragma unroll
                for (int tp = 0; tp < 4; tp++) {
                    int nrow = 16*tp + ((l>>4)<<3) + (l & 7);
                    int ko   = kc*16 + (((l>>3)&1) << 3);
                    uint32_t off = (uint32_t)(nrow*APITCH + ko*2);
                    ldsm4(bhf[2*tp][0],bhf[2*tp][1],bhf[2*tp+1][0],bhf[2*tp+1][1], stb + 0*AKPL + off);
                    ldsm4(blf[2*tp][0],blf[2*tp][1],blf[2*tp+1][0],blf[2*tp+1][1], stb + 1*AKPL + off);
                }
                #pragma unroll
                for (int t = 0; t < 8; t++) mma_bf16(s[t], qfh[kc], bhf[t]);
                #pragma unroll
                for (int t = 0; t < 8; t++) mma_bf16(s[t], qfh[kc], blf[t]);
                #pragma unroll
                for (int t = 0; t < 8; t++) mma_bf16(s[t], qfl[kc], bhf[t]);
            }
            // ---- causal mask (only near diagonal) ----
            if (k0 + 63 > qg0) {
                #pragma unroll
                for (int t = 0; t < 8; t++) {
                    int kg = k0 + 8*t + 2*(l & 3);
                    if (kg     > qg0) s[t][0] = -1e30f;
                    if (kg + 1 > qg0) s[t][1] = -1e30f;
                    if (kg     > qg1) s[t][2] = -1e30f;
                    if (kg + 1 > qg1) s[t][3] = -1e30f;
                }
            }
            // ---- online softmax (rows qg0, qg1) ----
            float mx0 = -1e30f, mx1 = -1e30f;
            #pragma unroll
            for (int t = 0; t < 8; t++) {
                mx0 = fmaxf(mx0, fmaxf(s[t][0], s[t][1]));
                mx1 = fmaxf(mx1, fmaxf(s[t][2], s[t][3]));
            }
            mx0 = fmaxf(mx0, __shfl_xor_sync(0xffffffffu, mx0, 1));
            mx0 = fmaxf(mx0, __shfl_xor_sync(0xffffffffu, mx0, 2));
            mx1 = fmaxf(mx1, __shfl_xor_sync(0xffffffffu, mx1, 1));
            mx1 = fmaxf(mx1, __shfl_xor_sync(0xffffffffu, mx1, 2));
            float mn0 = fmaxf(mr0, mx0), mn1 = fmaxf(mr1, mx1);
            float a0 = fexp(mr0 - mn0), a1 = fexp(mr1 - mn1);
            mr0 = mn0; mr1 = mn1;
            float rs0 = 0.f, rs1 = 0.f;
            #pragma unroll
            for (int t = 0; t < 8; t++) {
                s[t][0] = fexp(s[t][0] - mn0);
                s[t][1] = fexp(s[t][1] - mn0);
                s[t][2] = fexp(s[t][2] - mn1);
                s[t][3] = fexp(s[t][3] - mn1);
                rs0 += s[t][0] + s[t][1];
                rs1 += s[t][2] + s[t][3];
            }
            rs0 += __shfl_xor_sync(0xffffffffu, rs0, 1);
            rs0 += __shfl_xor_sync(0xffffffffu, rs0, 2);
            rs1 += __shfl_xor_sync(0xffffffffu, rs1, 1);
            rs1 += __shfl_xor_sync(0xffffffffu, rs1, 2);
            lr0 = lr0*a0 + rs0;
            lr1 = lr1*a1 + rs1;
            #pragma unroll
            for (int t = 0; t < 8; t++) {
                o[t][0] *= a0; o[t][1] *= a0; o[t][2] *= a1; o[t][3] *= a1;
            }
            // ---- P -> bf16 hi/lo A-fragments (registers only) ----
            uint32_t ph[4][4], pl[4][4];
            #pragma unroll
            for (int kc = 0; kc < 4; kc++) {
                int t0 = 2*kc, t1 = t0 + 1;
                float pv[4][2] = {{s[t0][0],s[t0][1]},{s[t0][2],s[t0][3]},
                                  {s[t1][0],s[t1][1]},{s[t1][2],s[t1][3]}};
                #pragma unroll
                for (int r = 0; r < 4; r++) {
                    uint32_t h = pack2(pv[r][0], pv[r][1]);
                    float h0 = __uint_as_float(h << 16);
                    float h1 = __uint_as_float(h & 0xffff0000u);
                    ph[kc][r] = h;
                    pl[kc][r] = pack2(pv[r][0] - h0, pv[r][1] - h1);
                }
            }
            // ---- O += P V (3-term), V via ldmatrix.trans ----
            #pragma unroll
            for (int kc = 0; kc < 4; kc++) {
                uint32_t vhf[8][2], vlf[8][2];
                #pragma unroll
                for (int tp = 0; tp < 4; tp++) {
                    int row = kc*16 + ((l>>3)&1)*8 + (l & 7);
                    int co  = 16*tp + ((l >> 4) << 3);
                    uint32_t off = (uint32_t)(row*APITCH + co*2);
                    ldsm4t(vhf[2*tp][0],vhf[2*tp][1],vhf[2*tp+1][0],vhf[2*tp+1][1], stb + 2*AKPL + off);
                    ldsm4t(vlf[2*tp][0],vlf[2*tp][1],vlf[2*tp+1][0],vlf[2*tp+1][1], stb + 3*AKPL + off);
                }
                #pragma unroll
                for (int t = 0; t < 8; t++) mma_bf16(o[t], ph[kc], vhf[t]);
                #pragma unroll
                for (int t = 0; t < 8; t++) mma_bf16(o[t], ph[kc], vlf[t]);
                #pragma unroll
                for (int t = 0; t < 8; t++) mma_bf16(o[t], pl[kc], vhf[t]);
            }
        }
        if (kt + 1 < nkt) { CPWAIT0(); __syncthreads(); }
    }

    // ---- epilogue: normalize, split to bf16 hi/lo, write [B,S,E] planes ----
    const float inv0 = 1.f / lr0, inv1 = 1.f / lr1;
    const int b = bh >> 4, h = bh & 15;
    const int s0 = qg0, s1 = qg1;
    #pragma unroll
    for (int t = 0; t < 8; t++) {
        int d = 8*t + 2*(l & 3);
        int e = h*HDIM + d;
        {
            float v0 = o[t][0]*inv0, v1 = o[t][1]*inv0;
            uint32_t hh = pack2(v0, v1);
            float h0 = __uint_as_float(hh << 16), h1 = __uint_as_float(hh & 0xffff0000u);
            uint32_t ll = pack2(v0 - h0, v1 - h1);
            size_t idx = ((size_t)b*SEQ + s0)*EMBED + e;
            *(uint32_t*)(g_ah + idx) = hh;
            *(uint32_t*)(g_al + idx) = ll;
        }
        {
            float v0 = o[t][2]*inv1, v1 = o[t][3]*inv1;
            uint32_t hh = pack2(v0, v1);
            float h0 = __uint_as_float(hh << 16), h1 = __uint_as_float(hh & 0xffff0000u);
            uint32_t ll = pack2(v0 - h0, v1 - h1);
            size_t idx = ((size_t)b*SEQ + s1)*EMBED + e;
            *(uint32_t*)(g_ah + idx) = hh;
            *(uint32_t*)(g_al + idx) = ll;
        }
    }
}

// ---------------------------------------------------------------------------
extern "C" void kernel_launch(void* const* d_in, const int* in_sizes, int n_in,
                              void* d_out, int out_size)
{
    const float* x  = (const float*)d_in[0];
    const float* Wq = (const float*)d_in[1];
    const float* Wk = (const float*)d_in[2];
    const float* Wv = (const float*)d_in[3];
    const float* Wo = (const float*)d_in[4];
    const float* bo = (const float*)d_in[5];
    float* out = (float*)d_out;

    cudaFuncSetAttribute(gemm_kernel, cudaFuncAttributeMaxDynamicSharedMemorySize, GSMEM);
    cudaFuncSetAttribute(attn_kernel, cudaFuncAttributeMaxDynamicSharedMemorySize, ASMEM);

    prep_kernel<<<dim3(32, 32, 8), dim3(32, 8)>>>(x, Wq, Wk, Wv, Wo);

    gemm_kernel<<<dim3(4, 32, 3), 512, GSMEM>>>(nullptr, nullptr, 0);  // QKV
    attn_kernel<<<dim3(32, 32), 128, ASMEM>>>();                       // attention
    gemm_kernel<<<dim3(4, 32, 1), 512, GSMEM>>>(out, bo, 1);           // O-proj
}

// round 12
// speedup vs baseline: 1.5473x; 1.3334x over previous
#include <cuda_runtime.h>
#include <cuda_fp16.h>
#include <cstdint>
#include <math.h>

#define BATCH  2
#define SEQ    2048
#define EMBED  1024
#define NHEADS 16
#define HDIM   64
#define MROWS  4096
#define MATSZ  (MROWS*EMBED)     // 4194304
#define WSZ    (EMBED*EMBED)     // 1048576

// ---------------------------------------------------------------------------
// Scratch planes (__device__ globals; allocation-free rule)
// fp16 2-term scheme: activations single-plane, weight-like operands hi/lo.
// ---------------------------------------------------------------------------
__device__ __half g_x[MATSZ];                      // x (single) [M,K]
__device__ __half g_wh[4*WSZ], g_wl[4*WSZ];        // W^T hi/lo  [N,K] (q,k,v,o)
__device__ __half g_qkv[3*MATSZ];                  // q,k,v single planes [B,H,S,D]
__device__ __half g_kl[MATSZ];                     // k lo plane
__device__ __half g_a[MATSZ];                      // attn out (single) [M,E]

// ---------------------------------------------------------------------------
// Helpers
// ---------------------------------------------------------------------------
__device__ __forceinline__ uint32_t s2u(const void* p){
    uint32_t a;
    asm("{ .reg .u64 t; cvta.to.shared.u64 t, %1; cvt.u32.u64 %0, t; }" : "=r"(a) : "l"(p));
    return a;
}
__device__ __forceinline__ uint32_t pack2h(float lo, float hi){
    __half2 v = __halves2half2(__float2half(lo), __float2half(hi));
    return *reinterpret_cast<uint32_t*>(&v);
}
__device__ __forceinline__ float2 unpack2h(uint32_t u){
    __half2 v = *reinterpret_cast<__half2*>(&u);
    return __half22float2(v);
}
__device__ __forceinline__ void ldsm4(uint32_t& r0,uint32_t& r1,uint32_t& r2,uint32_t& r3,uint32_t a){
    asm volatile("ldmatrix.sync.aligned.m8n8.x4.shared.b16 {%0,%1,%2,%3}, [%4];"
        : "=r"(r0),"=r"(r1),"=r"(r2),"=r"(r3) : "r"(a));
}
__device__ __forceinline__ void ldsm4t(uint32_t& r0,uint32_t& r1,uint32_t& r2,uint32_t& r3,uint32_t a){
    asm volatile("ldmatrix.sync.aligned.m8n8.x4.trans.shared.b16 {%0,%1,%2,%3}, [%4];"
        : "=r"(r0),"=r"(r1),"=r"(r2),"=r"(r3) : "r"(a));
}
__device__ __forceinline__ void mma_fp16(float* c, const uint32_t* a, const uint32_t* b){
    asm volatile("mma.sync.aligned.m16n8k16.row.col.f32.f16.f16.f32 "
        "{%0,%1,%2,%3}, {%4,%5,%6,%7}, {%8,%9}, {%0,%1,%2,%3};"
        : "+f"(c[0]),"+f"(c[1]),"+f"(c[2]),"+f"(c[3])
        : "r"(a[0]),"r"(a[1]),"r"(a[2]),"r"(a[3]), "r"(b[0]),"r"(b[1]));
}
__device__ __forceinline__ void cpa16(uint32_t dst, const void* src){
    asm volatile("cp.async.cg.shared.global [%0], [%1], 16;" :: "r"(dst), "l"(src));
}
#define CPCOMMIT() asm volatile("cp.async.commit_group;" ::: "memory")
#define CPWAIT0()  asm volatile("cp.async.wait_group 0;" ::: "memory")

// FMA-only exp (x <= 0 path): ~3e-6 rel err, no MUFU.
__device__ __forceinline__ float fexp(float x){
    float y = x * 1.4426950408889634f;
    y = fmaxf(y, -126.0f);
    float t = y + 12582912.0f;               // round-to-nearest
    int   n = __float_as_int(t) - 0x4B400000;
    float f = y - (t - 12582912.0f);         // f in [-0.5, 0.5]
    float p = 1.3333558146e-3f;
    p = fmaf(p, f, 9.6181291076e-3f);
    p = fmaf(p, f, 5.5504108665e-2f);
    p = fmaf(p, f, 2.4022650696e-1f);
    p = fmaf(p, f, 6.9314718056e-1f);
    p = fmaf(p, f, 1.0f);
    return __int_as_float(__float_as_int(p) + (n << 23));
}

// ---------------------------------------------------------------------------
// Fused prep: z 0..3 -> transpose+split W hi/lo (q,k,v,o); z 4..7 -> x single
// block = (32, 8) = 256 threads
// ---------------------------------------------------------------------------
__global__ __launch_bounds__(256) void prep_kernel(
    const float* __restrict__ x,
    const float* __restrict__ Wq, const float* __restrict__ Wk,
    const float* __restrict__ Wv, const float* __restrict__ Wo)
{
    __shared__ float t[32][33];
    const int z = blockIdx.z;
    const int tx = threadIdx.x, ty = threadIdx.y;

    if (z >= 4) {
        int b = (z - 4)*1024 + blockIdx.y*32 + blockIdx.x;
        int i = b*256 + ty*32 + tx;
        float4 v = ((const float4*)x)[i];
        ((uint2*)g_x)[i] = make_uint2(pack2h(v.x, v.y), pack2h(v.z, v.w));
        return;
    }

    const float* W = (z==0)?Wq:(z==1)?Wk:(z==2)?Wv:Wo;
    __half* Oh = g_wh + (size_t)z*WSZ;
    __half* Ol = g_wl + (size_t)z*WSZ;
    int nb = blockIdx.x*32, kb = blockIdx.y*32;
    #pragma unroll
    for (int r = 0; r < 4; r++)
        t[ty + r*8][tx] = W[(size_t)(kb + ty + r*8)*EMBED + nb + tx];
    __syncthreads();
    #pragma unroll
    for (int r = 0; r < 4; r++) {
        float v = t[tx][ty + r*8];
        __half hb = __float2half(v);
        size_t o = (size_t)(nb + ty + r*8)*EMBED + kb + tx;
        Oh[o] = hb;
        Ol[o] = __float2half(v - __half2float(hb));
    }
}

// ---------------------------------------------------------------------------
// mma.sync fp16 2-term GEMM: D[M,N] = A[M,K] @ (Bh+Bl)^T[N,K]
// CTA 128x256, 512 threads, 16 warps (4m x 4n), warp 32x64, KC=32, 2-stage.
// mode 0: A = x, B = W_{q,k,v}(z); epilogue -> q/v single, k hi+lo planes
// mode 1: A = attn out, B = W_o; epilogue -> fp32 out + bias
// ---------------------------------------------------------------------------
#define GKC 32
#define GNCH (EMBED/GKC)         // 32 chunks
#define GPITCH 80
#define GAPL  (128*GPITCH)       // 10240 (A plane)
#define GBPL  (256*GPITCH)       // 20480 (B plane)
#define GB_OFF GAPL
#define GSTAGE (GAPL + 2*GBPL)   // 51200
#define GSMEM  (2*GSTAGE)        // 102400

__global__ __launch_bounds__(512,1) void gemm_kernel(float* __restrict__ out,
                                                     const float* __restrict__ bias,
                                                     int mode)
{
    extern __shared__ char smg[];
    const uint32_t sb = s2u(smg);
    const int tid = threadIdx.x, l = tid & 31, wid = tid >> 5;
    const int wm = wid >> 2, wn = wid & 3;
    const int m0 = blockIdx.y * 128, n0 = blockIdx.x * 256;
    const int z = blockIdx.z;

    const __half *Ap, *Bh, *Bl;
    if (mode == 0) {
        Ap = g_x;
        Bh = g_wh + (size_t)z*WSZ; Bl = g_wl + (size_t)z*WSZ;
    } else {
        Ap = g_a;
        Bh = g_wh + 3*(size_t)WSZ; Bl = g_wl + 3*(size_t)WSZ;
    }

    auto load_stage = [&](int c){
        const uint32_t sbase = sb + (c & 1)*GSTAGE;
        const int k0 = c * GKC;
        {   // A: 1 plane x 128 rows x 4 ch = 512
            int row = tid >> 2, ch = tid & 3;
            cpa16(sbase + row*GPITCH + ch*16,
                  Ap + (size_t)(m0 + row)*EMBED + k0 + ch*8);
        }
        #pragma unroll
        for (int i = 0; i < 4; i++) {        // B: 2 planes x 256 rows x 4 ch
            int g   = i*512 + tid;
            int p   = g >> 10;
            int row = (g >> 2) & 255;
            int ch  = g & 3;
            const __half* src = p ? Bl : Bh;
            cpa16(sbase + GB_OFF + p*GBPL + row*GPITCH + ch*16,
                  src + (size_t)(n0 + row)*EMBED + k0 + ch*8);
        }
        CPCOMMIT();
    };

    float acc[2][8][4];
    #pragma unroll
    for (int i = 0; i < 2; i++)
        #pragma unroll
        for (int t = 0; t < 8; t++)
            #pragma unroll
            for (int j = 0; j < 4; j++) acc[i][t][j] = 0.f;

    load_stage(0);
    for (int c = 0; c < GNCH; c++) {
        CPWAIT0();
        __syncthreads();
        if (c + 1 < GNCH) load_stage(c + 1);
        const uint32_t stb = sb + (c & 1)*GSTAGE;
        #pragma unroll
        for (int kk = 0; kk < 2; kk++) {
            uint32_t ah[2][4], bf[8][2];
            #pragma unroll
            for (int i = 0; i < 2; i++) {
                int row = 32*wm + 16*i + (l & 15);
                int ko  = kk*16 + ((l >> 4) << 3);
                uint32_t off = (uint32_t)(row*GPITCH + ko*2);
                ldsm4(ah[i][0],ah[i][1],ah[i][2],ah[i][3], stb + off);
            }
            {   // B-hi
                #pragma unroll
                for (int tp = 0; tp < 4; tp++) {
                    int nrow = 64*wn + 16*tp + ((l>>4)<<3) + (l & 7);
                    int ko   = kk*16 + (((l>>3)&1) << 3);
                    uint32_t off = (uint32_t)(nrow*GPITCH + ko*2);
                    ldsm4(bf[2*tp][0],bf[2*tp][1],bf[2*tp+1][0],bf[2*tp+1][1],
                          stb + GB_OFF + 0*GBPL + off);
                }
                #pragma unroll
                for (int i = 0; i < 2; i++)
                    #pragma unroll
                    for (int t = 0; t < 8; t++) mma_fp16(acc[i][t], ah[i], bf[t]);
            }
            {   // B-lo (reuse buffer)
                #pragma unroll
                for (int tp = 0; tp < 4; tp++) {
                    int nrow = 64*wn + 16*tp + ((l>>4)<<3) + (l & 7);
                    int ko   = kk*16 + (((l>>3)&1) << 3);
                    uint32_t off = (uint32_t)(nrow*GPITCH + ko*2);
                    ldsm4(bf[2*tp][0],bf[2*tp][1],bf[2*tp+1][0],bf[2*tp+1][1],
                          stb + GB_OFF + 1*GBPL + off);
                }
                #pragma unroll
                for (int i = 0; i < 2; i++)
                    #pragma unroll
                    for (int t = 0; t < 8; t++) mma_fp16(acc[i][t], ah[i], bf[t]);
            }
        }
    }

    // epilogue
    if (mode == 1) {
        #pragma unroll
        for (int i = 0; i < 2; i++)
            #pragma unroll
            for (int t = 0; t < 8; t++)
                #pragma unroll
                for (int rr = 0; rr < 2; rr++) {
                    int m = m0 + 32*wm + 16*i + (l>>2) + 8*rr;
                    int n = n0 + 64*wn + 8*t + 2*(l&3);
                    float2 v = make_float2(acc[i][t][2*rr]   + bias[n],
                                           acc[i][t][2*rr+1] + bias[n+1]);
                    *(float2*)&out[(size_t)m*EMBED + n] = v;
                }
    } else {
        __half* oh = g_qkv + (size_t)z*MATSZ;
        const float scl = (z == 0) ? 0.125f : 1.0f;   // fold 1/sqrt(D) into Q
        #pragma unroll
        for (int i = 0; i < 2; i++)
            #pragma unroll
            for (int t = 0; t < 8; t++)
                #pragma unroll
                for (int rr = 0; rr < 2; rr++) {
                    int m = m0 + 32*wm + 16*i + (l>>2) + 8*rr;
                    int n = n0 + 64*wn + 8*t + 2*(l&3);
                    float v0 = acc[i][t][2*rr]*scl, v1 = acc[i][t][2*rr+1]*scl;
                    uint32_t h = pack2h(v0, v1);
                    int b = m >> 11, s = m & 2047, hh = n >> 6, d = n & 63;
                    size_t idx = ((((size_t)b*NHEADS + hh)*SEQ) + s)*HDIM + d;
                    *(uint32_t*)(oh + idx) = h;
                    if (z == 1) {   // K: also write lo plane
                        float2 hf = unpack2h(h);
                        *(uint32_t*)(g_kl + idx) = pack2h(v0 - hf.x, v1 - hf.y);
                    }
                }
    }
}

// ---------------------------------------------------------------------------
// Flash attention, fp16 2-term. CTA = 64 q-rows; 4 warps; 3 CTAs/SM.
// S = Q*(Kh+Kl)^T, O += (Ph+Pl)*V. Q/V single planes.
// ---------------------------------------------------------------------------
#define APITCH 144
#define AKPL   (64*APITCH)         // 9216
#define ASTAGE (3*AKPL)            // 27648 (Kh, Kl, V)
#define ASMEM  (2*ASTAGE)          // 55296

__global__ __launch_bounds__(128,3) void attn_kernel()
{
    extern __shared__ char sma[];
    const uint32_t sb = s2u(sma);
    const int tid = threadIdx.x, l = tid & 31, wid = tid >> 5;
    const int qt = 31 - (int)blockIdx.x;        // heavy tiles first
    const int bh = blockIdx.y;
    const int q0 = qt * 64;
    const int nkt = qt + 1;
    const size_t base = (size_t)bh * SEQ * HDIM;
    const __half *Qg = g_qkv + base;
    const __half *Kh = g_qkv + MATSZ + base;
    const __half *Kl = g_kl + base;
    const __half *Vg = g_qkv + 2*(size_t)MATSZ + base;

    // ---- stream Q plane through stage-0 buffer, extract register frags ----
    #pragma unroll
    for (int i = 0; i < 4; i++) {
        int g = i*128 + tid;
        int row = (g >> 3) & 63, ch = g & 7;
        cpa16(sb + row*APITCH + ch*16, Qg + (size_t)(q0 + row)*HDIM + ch*8);
    }
    CPCOMMIT();
    CPWAIT0();
    __syncthreads();

    uint32_t qf[4][4];
    {
        int row = 16*wid + (l & 15);
        #pragma unroll
        for (int kc = 0; kc < 4; kc++) {
            int ko = kc*16 + ((l >> 4) << 3);
            uint32_t off = (uint32_t)(row*APITCH + ko*2);
            ldsm4(qf[kc][0],qf[kc][1],qf[kc][2],qf[kc][3], sb + off);
        }
    }
    __syncthreads();   // all warps done reading Q before buffer reuse

    auto load_kv = [&](int kt){
        const uint32_t stb = sb + (kt & 1)*ASTAGE;
        const int k0 = kt * 64;
        #pragma unroll
        for (int i = 0; i < 12; i++) {
            int g = i*128 + tid;
            int p = g >> 9, row = (g >> 3) & 63, ch = g & 7;  // p: 0 Kh 1 Kl 2 V
            const __half* src = (p==0)?Kh:(p==1)?Kl:Vg;
            cpa16(stb + p*AKPL + row*APITCH + ch*16,
                  src + (size_t)(k0 + row)*HDIM + ch*8);
        }
        CPCOMMIT();
    };
    load_kv(0);
    CPWAIT0();
    __syncthreads();

    float o[8][4];
    #pragma unroll
    for (int t = 0; t < 8; t++)
        #pragma unroll
        for (int j = 0; j < 4; j++) o[t][j] = 0.f;
    float mr0 = -1e30f, mr1 = -1e30f, lr0 = 0.f, lr1 = 0.f;
    const int qg0 = q0 + 16*wid + (l >> 2);
    const int qg1 = qg0 + 8;

    for (int kt = 0; kt < nkt; kt++) {
        if (kt + 1 < nkt) load_kv(kt + 1);
        const uint32_t stb = sb + (kt & 1)*ASTAGE;
        const int k0 = kt * 64;

        {
            // ---- S = Q (Kh+Kl)^T ----
            float s[8][4];
            #pragma unroll
            for (int t = 0; t < 8; t++)
                #pragma unroll
                for (int j = 0; j < 4; j++) s[t][j] = 0.f;
            #pragma unroll
            for (int kc = 0; kc < 4; kc++) {
                uint32_t bf[8][2];
                #pragma unroll
                for (int tp = 0; tp < 4; tp++) {
                    int nrow = 16*tp + ((l>>4)<<3) + (l & 7);
                    int ko   = kc*16 + (((l>>3)&1) << 3);
                    uint32_t off = (uint32_t)(nrow*APITCH + ko*2);
                    ldsm4(bf[2*tp][0],bf[2*tp][1],bf[2*tp+1][0],bf[2*tp+1][1], stb + 0*AKPL + off);
                }
                #pragma unroll
                for (int t = 0; t < 8; t++) mma_fp16(s[t], qf[kc], bf[t]);
                #pragma unroll
                for (int tp = 0; tp < 4; tp++) {
                    int nrow = 16*tp + ((l>>4)<<3) + (l & 7);
                    int ko   = kc*16 + (((l>>3)&1) << 3);
                    uint32_t off = (uint32_t)(nrow*APITCH + ko*2);
                    ldsm4(bf[2*tp][0],bf[2*tp][1],bf[2*tp+1][0],bf[2*tp+1][1], stb + 1*AKPL + off);
                }
                #pragma unroll
                for (int t = 0; t < 8; t++) mma_fp16(s[t], qf[kc], bf[t]);
            }
            // ---- causal mask (only near diagonal) ----
            if (k0 + 63 > qg0) {
                #pragma unroll
                for (int t = 0; t < 8; t++) {
                    int kg = k0 + 8*t + 2*(l & 3);
                    if (kg     > qg0) s[t][0] = -1e30f;
                    if (kg + 1 > qg0) s[t][1] = -1e30f;
                    if (kg     > qg1) s[t][2] = -1e30f;
                    if (kg + 1 > qg1) s[t][3] = -1e30f;
                }
            }
            // ---- online softmax (rows qg0, qg1) ----
            float mx0 = -1e30f, mx1 = -1e30f;
            #pragma unroll
            for (int t = 0; t < 8; t++) {
                mx0 = fmaxf(mx0, fmaxf(s[t][0], s[t][1]));
                mx1 = fmaxf(mx1, fmaxf(s[t][2], s[t][3]));
            }
            mx0 = fmaxf(mx0, __shfl_xor_sync(0xffffffffu, mx0, 1));
            mx0 = fmaxf(mx0, __shfl_xor_sync(0xffffffffu, mx0, 2));
            mx1 = fmaxf(mx1, __shfl_xor_sync(0xffffffffu, mx1, 1));
            mx1 = fmaxf(mx1, __shfl_xor_sync(0xffffffffu, mx1, 2));
            float mn0 = fmaxf(mr0, mx0), mn1 = fmaxf(mr1, mx1);
            float a0 = fexp(mr0 - mn0), a1 = fexp(mr1 - mn1);
            mr0 = mn0; mr1 = mn1;
            float rs0 = 0.f, rs1 = 0.f;
            #pragma unroll
            for (int t = 0; t < 8; t++) {
                s[t][0] = fexp(s[t][0] - mn0);
                s[t][1] = fexp(s[t][1] - mn0);
                s[t][2] = fexp(s[t][2] - mn1);
                s[t][3] = fexp(s[t][3] - mn1);
                rs0 += s[t][0] + s[t][1];
                rs1 += s[t][2] + s[t][3];
            }
            rs0 += __shfl_xor_sync(0xffffffffu, rs0, 1);
            rs0 += __shfl_xor_sync(0xffffffffu, rs0, 2);
            rs1 += __shfl_xor_sync(0xffffffffu, rs1, 1);
            rs1 += __shfl_xor_sync(0xffffffffu, rs1, 2);
            lr0 = lr0*a0 + rs0;
            lr1 = lr1*a1 + rs1;
            #pragma unroll
            for (int t = 0; t < 8; t++) {
                o[t][0] *= a0; o[t][1] *= a0; o[t][2] *= a1; o[t][3] *= a1;
            }
            // ---- P -> fp16 hi/lo A-fragments (registers only) ----
            uint32_t ph[4][4], pl[4][4];
            #pragma unroll
            for (int kc = 0; kc < 4; kc++) {
                int t0 = 2*kc, t1 = t0 + 1;
                float pv[4][2] = {{s[t0][0],s[t0][1]},{s[t0][2],s[t0][3]},
                                  {s[t1][0],s[t1][1]},{s[t1][2],s[t1][3]}};
                #pragma unroll
                for (int r = 0; r < 4; r++) {
                    uint32_t h = pack2h(pv[r][0], pv[r][1]);
                    float2 hf = unpack2h(h);
                    ph[kc][r] = h;
                    pl[kc][r] = pack2h(pv[r][0] - hf.x, pv[r][1] - hf.y);
                }
            }
            // ---- O += (Ph+Pl) V, V via ldmatrix.trans ----
            #pragma unroll
            for (int kc = 0; kc < 4; kc++) {
                uint32_t vf[8][2];
                #pragma unroll
                for (int tp = 0; tp < 4; tp++) {
                    int row = kc*16 + ((l>>3)&1)*8 + (l & 7);
                    int co  = 16*tp + ((l >> 4) << 3);
                    uint32_t off = (uint32_t)(row*APITCH + co*2);
                    ldsm4t(vf[2*tp][0],vf[2*tp][1],vf[2*tp+1][0],vf[2*tp+1][1], stb + 2*AKPL + off);
                }
                #pragma unroll
                for (int t = 0; t < 8; t++) mma_fp16(o[t], ph[kc], vf[t]);
                #pragma unroll
                for (int t = 0; t < 8; t++) mma_fp16(o[t], pl[kc], vf[t]);
            }
        }
        if (kt + 1 < nkt) { CPWAIT0(); __syncthreads(); }
    }

    // ---- epilogue: normalize, write fp16 single plane [B,S,E] ----
    const float inv0 = 1.f / lr0, inv1 = 1.f / lr1;
    const int b = bh >> 4, h = bh & 15;
    const int s0 = qg0, s1 = qg1;
    #pragma unroll
    for (int t = 0; t < 8; t++) {
        int d = 8*t + 2*(l & 3);
        int e = h*HDIM + d;
        *(uint32_t*)(g_a + ((size_t)b*SEQ + s0)*EMBED + e) =
            pack2h(o[t][0]*inv0, o[t][1]*inv0);
        *(uint32_t*)(g_a + ((size_t)b*SEQ + s1)*EMBED + e) =
            pack2h(o[t][2]*inv1, o[t][3]*inv1);
    }
}

// ---------------------------------------------------------------------------
extern "C" void kernel_launch(void* const* d_in, const int* in_sizes, int n_in,
                              void* d_out, int out_size)
{
    const float* x  = (const float*)d_in[0];
    const float* Wq = (const float*)d_in[1];
    const float* Wk = (const float*)d_in[2];
    const float* Wv = (const float*)d_in[3];
    const float* Wo = (const float*)d_in[4];
    const float* bo = (const float*)d_in[5];
    float* out = (float*)d_out;

    cudaFuncSetAttribute(gemm_kernel, cudaFuncAttributeMaxDynamicSharedMemorySize, GSMEM);
    cudaFuncSetAttribute(attn_kernel, cudaFuncAttributeMaxDynamicSharedMemorySize, ASMEM);

    prep_kernel<<<dim3(32, 32, 8), dim3(32, 8)>>>(x, Wq, Wk, Wv, Wo);

    gemm_kernel<<<dim3(4, 32, 3), 512, GSMEM>>>(nullptr, nullptr, 0);  // QKV
    attn_kernel<<<dim3(32, 32), 128, ASMEM>>>();                       // attention
    gemm_kernel<<<dim3(4, 32, 1), 512, GSMEM>>>(out, bo, 1);           // O-proj
}

// round 13
// speedup vs baseline: 2.3739x; 1.5342x over previous
#include <cuda_runtime.h>
#include <cuda_fp16.h>
#include <cstdint>
#include <math.h>

#define BATCH  2
#define SEQ    2048
#define EMBED  1024
#define NHEADS 16
#define HDIM   64
#define MROWS  4096
#define MATSZ  (MROWS*EMBED)     // 4194304
#define WSZ    (EMBED*EMBED)     // 1048576

// ---------------------------------------------------------------------------
// Scratch planes (__device__ globals; allocation-free rule)
// Plain fp16 single-term pipeline (fp32 accumulate in all MMAs).
// ---------------------------------------------------------------------------
__device__ __half g_x[MATSZ];          // x fp16 [M,K]
__device__ __half g_wt[4*WSZ];         // W^T fp16 [N,K] (q,k,v,o)
__device__ __half g_qkv[3*MATSZ];      // q,k,v fp16 [B,H,S,D]
__device__ __half g_a[MATSZ];          // attn out fp16 [M,E]

// ---------------------------------------------------------------------------
// Helpers
// ---------------------------------------------------------------------------
__device__ __forceinline__ uint32_t s2u(const void* p){
    uint32_t a;
    asm("{ .reg .u64 t; cvta.to.shared.u64 t, %1; cvt.u32.u64 %0, t; }" : "=r"(a) : "l"(p));
    return a;
}
__device__ __forceinline__ uint32_t pack2h(float lo, float hi){
    __half2 v = __halves2half2(__float2half(lo), __float2half(hi));
    return *reinterpret_cast<uint32_t*>(&v);
}
__device__ __forceinline__ void ldsm4(uint32_t& r0,uint32_t& r1,uint32_t& r2,uint32_t& r3,uint32_t a){
    asm volatile("ldmatrix.sync.aligned.m8n8.x4.shared.b16 {%0,%1,%2,%3}, [%4];"
        : "=r"(r0),"=r"(r1),"=r"(r2),"=r"(r3) : "r"(a));
}
__device__ __forceinline__ void ldsm4t(uint32_t& r0,uint32_t& r1,uint32_t& r2,uint32_t& r3,uint32_t a){
    asm volatile("ldmatrix.sync.aligned.m8n8.x4.trans.shared.b16 {%0,%1,%2,%3}, [%4];"
        : "=r"(r0),"=r"(r1),"=r"(r2),"=r"(r3) : "r"(a));
}
__device__ __forceinline__ void mma_fp16(float* c, const uint32_t* a, const uint32_t* b){
    asm volatile("mma.sync.aligned.m16n8k16.row.col.f32.f16.f16.f32 "
        "{%0,%1,%2,%3}, {%4,%5,%6,%7}, {%8,%9}, {%0,%1,%2,%3};"
        : "+f"(c[0]),"+f"(c[1]),"+f"(c[2]),"+f"(c[3])
        : "r"(a[0]),"r"(a[1]),"r"(a[2]),"r"(a[3]), "r"(b[0]),"r"(b[1]));
}
__device__ __forceinline__ void cpa16(uint32_t dst, const void* src){
    asm volatile("cp.async.cg.shared.global [%0], [%1], 16;" :: "r"(dst), "l"(src));
}
#define CPCOMMIT() asm volatile("cp.async.commit_group;" ::: "memory")
#define CPWAIT0()  asm volatile("cp.async.wait_group 0;" ::: "memory")

// FMA-only exp (x <= 0 path): ~3e-6 rel err, no MUFU.
__device__ __forceinline__ float fexp(float x){
    float y = x * 1.4426950408889634f;
    y = fmaxf(y, -126.0f);
    float t = y + 12582912.0f;               // round-to-nearest
    int   n = __float_as_int(t) - 0x4B400000;
    float f = y - (t - 12582912.0f);         // f in [-0.5, 0.5]
    float p = 1.3333558146e-3f;
    p = fmaf(p, f, 9.6181291076e-3f);
    p = fmaf(p, f, 5.5504108665e-2f);
    p = fmaf(p, f, 2.4022650696e-1f);
    p = fmaf(p, f, 6.9314718056e-1f);
    p = fmaf(p, f, 1.0f);
    return __int_as_float(__float_as_int(p) + (n << 23));
}

// ---------------------------------------------------------------------------
// Fused prep: z 0..3 -> transpose W (q,k,v,o) to fp16; z 4..7 -> convert x
// block = (32, 8) = 256 threads
// ---------------------------------------------------------------------------
__global__ __launch_bounds__(256) void prep_kernel(
    const float* __restrict__ x,
    const float* __restrict__ Wq, const float* __restrict__ Wk,
    const float* __restrict__ Wv, const float* __restrict__ Wo)
{
    __shared__ float t[32][33];
    const int z = blockIdx.z;
    const int tx = threadIdx.x, ty = threadIdx.y;

    if (z >= 4) {
        int b = (z - 4)*1024 + blockIdx.y*32 + blockIdx.x;
        int i = b*256 + ty*32 + tx;
        float4 v = ((const float4*)x)[i];
        ((uint2*)g_x)[i] = make_uint2(pack2h(v.x, v.y), pack2h(v.z, v.w));
        return;
    }

    const float* W = (z==0)?Wq:(z==1)?Wk:(z==2)?Wv:Wo;
    __half* O = g_wt + (size_t)z*WSZ;
    int nb = blockIdx.x*32, kb = blockIdx.y*32;
    #pragma unroll
    for (int r = 0; r < 4; r++)
        t[ty + r*8][tx] = W[(size_t)(kb + ty + r*8)*EMBED + nb + tx];
    __syncthreads();
    #pragma unroll
    for (int r = 0; r < 4; r++)
        O[(size_t)(nb + ty + r*8)*EMBED + kb + tx] = __float2half(t[tx][ty + r*8]);
}

// ---------------------------------------------------------------------------
// mma.sync fp16 GEMM: D[M,N] = A[M,K] @ B^T[N,K]
// CTA 128x256, 512 threads, 16 warps (4m x 4n), warp 32x64, KC=32, 2-stage.
// mode 0: A = x, B = W_{q,k,v}(z); epilogue -> fp16 qkv planes
// mode 1: A = attn out, B = W_o; epilogue -> fp32 out + bias
// ---------------------------------------------------------------------------
#define GKC 32
#define GNCH (EMBED/GKC)         // 32 chunks
#define GPITCH 80
#define GAPL  (128*GPITCH)       // 10240 (A plane)
#define GBPL  (256*GPITCH)       // 20480 (B plane)
#define GB_OFF GAPL
#define GSTAGE (GAPL + GBPL)     // 30720
#define GSMEM  (2*GSTAGE)        // 61440

__global__ __launch_bounds__(512,1) void gemm_kernel(float* __restrict__ out,
                                                     const float* __restrict__ bias,
                                                     int mode)
{
    extern __shared__ char smg[];
    const uint32_t sb = s2u(smg);
    const int tid = threadIdx.x, l = tid & 31, wid = tid >> 5;
    const int wm = wid >> 2, wn = wid & 3;
    const int m0 = blockIdx.y * 128, n0 = blockIdx.x * 256;
    const int z = blockIdx.z;

    const __half *Ap, *Bp;
    if (mode == 0) { Ap = g_x; Bp = g_wt + (size_t)z*WSZ; }
    else           { Ap = g_a; Bp = g_wt + 3*(size_t)WSZ; }

    auto load_stage = [&](int c){
        const uint32_t sbase = sb + (c & 1)*GSTAGE;
        const int k0 = c * GKC;
        {   // A: 128 rows x 4 ch = 512 cp.async
            int row = tid >> 2, ch = tid & 3;
            cpa16(sbase + row*GPITCH + ch*16,
                  Ap + (size_t)(m0 + row)*EMBED + k0 + ch*8);
        }
        #pragma unroll
        for (int i = 0; i < 2; i++) {        // B: 256 rows x 4 ch = 1024
            int g   = i*512 + tid;
            int row = (g >> 2) & 255;
            int ch  = g & 3;
            cpa16(sbase + GB_OFF + row*GPITCH + ch*16,
                  Bp + (size_t)(n0 + row)*EMBED + k0 + ch*8);
        }
        CPCOMMIT();
    };

    float acc[2][8][4];
    #pragma unroll
    for (int i = 0; i < 2; i++)
        #pragma unroll
        for (int t = 0; t < 8; t++)
            #pragma unroll
            for (int j = 0; j < 4; j++) acc[i][t][j] = 0.f;

    load_stage(0);
    for (int c = 0; c < GNCH; c++) {
        CPWAIT0();
        __syncthreads();
        if (c + 1 < GNCH) load_stage(c + 1);
        const uint32_t stb = sb + (c & 1)*GSTAGE;
        #pragma unroll
        for (int kk = 0; kk < 2; kk++) {
            uint32_t ah[2][4], bf[8][2];
            #pragma unroll
            for (int i = 0; i < 2; i++) {
                int row = 32*wm + 16*i + (l & 15);
                int ko  = kk*16 + ((l >> 4) << 3);
                uint32_t off = (uint32_t)(row*GPITCH + ko*2);
                ldsm4(ah[i][0],ah[i][1],ah[i][2],ah[i][3], stb + off);
            }
            #pragma unroll
            for (int tp = 0; tp < 4; tp++) {
                int nrow = 64*wn + 16*tp + ((l>>4)<<3) + (l & 7);
                int ko   = kk*16 + (((l>>3)&1) << 3);
                uint32_t off = (uint32_t)(nrow*GPITCH + ko*2);
                ldsm4(bf[2*tp][0],bf[2*tp][1],bf[2*tp+1][0],bf[2*tp+1][1],
                      stb + GB_OFF + off);
            }
            #pragma unroll
            for (int i = 0; i < 2; i++)
                #pragma unroll
                for (int t = 0; t < 8; t++) mma_fp16(acc[i][t], ah[i], bf[t]);
        }
    }

    // epilogue
    if (mode == 1) {
        #pragma unroll
        for (int i = 0; i < 2; i++)
            #pragma unroll
            for (int t = 0; t < 8; t++)
                #pragma unroll
                for (int rr = 0; rr < 2; rr++) {
                    int m = m0 + 32*wm + 16*i + (l>>2) + 8*rr;
                    int n = n0 + 64*wn + 8*t + 2*(l&3);
                    float2 v = make_float2(acc[i][t][2*rr]   + bias[n],
                                           acc[i][t][2*rr+1] + bias[n+1]);
                    *(float2*)&out[(size_t)m*EMBED + n] = v;
                }
    } else {
        __half* oh = g_qkv + (size_t)z*MATSZ;
        const float scl = (z == 0) ? 0.125f : 1.0f;   // fold 1/sqrt(D) into Q
        #pragma unroll
        for (int i = 0; i < 2; i++)
            #pragma unroll
            for (int t = 0; t < 8; t++)
                #pragma unroll
                for (int rr = 0; rr < 2; rr++) {
                    int m = m0 + 32*wm + 16*i + (l>>2) + 8*rr;
                    int n = n0 + 64*wn + 8*t + 2*(l&3);
                    uint32_t h = pack2h(acc[i][t][2*rr]*scl, acc[i][t][2*rr+1]*scl);
                    int b = m >> 11, s = m & 2047, hh = n >> 6, d = n & 63;
                    size_t idx = ((((size_t)b*NHEADS + hh)*SEQ) + s)*HDIM + d;
                    *(uint32_t*)(oh + idx) = h;
                }
    }
}

// ---------------------------------------------------------------------------
// Flash attention, plain fp16. CTA = 64 q-rows; 4 warps; 3 CTAs/SM.
// S = Q K^T, O += P V, single-term, fp32 accumulate + fp32 softmax.
// ---------------------------------------------------------------------------
#define APITCH 144
#define AKPL   (64*APITCH)         // 9216
#define ASTAGE (2*AKPL)            // 18432 (K, V)
#define ASMEM  (2*ASTAGE)          // 36864

__global__ __launch_bounds__(128,3) void attn_kernel()
{
    extern __shared__ char sma[];
    const uint32_t sb = s2u(sma);
    const int tid = threadIdx.x, l = tid & 31, wid = tid >> 5;
    const int qt = 31 - (int)blockIdx.x;        // heavy tiles first
    const int bh = blockIdx.y;
    const int q0 = qt * 64;
    const int nkt = qt + 1;
    const size_t base = (size_t)bh * SEQ * HDIM;
    const __half *Qg = g_qkv + base;
    const __half *Kg = g_qkv + MATSZ + base;
    const __half *Vg = g_qkv + 2*(size_t)MATSZ + base;

    // ---- stream Q plane through stage-0 buffer, extract register frags ----
    #pragma unroll
    for (int i = 0; i < 4; i++) {
        int g = i*128 + tid;
        int row = (g >> 3) & 63, ch = g & 7;
        cpa16(sb + row*APITCH + ch*16, Qg + (size_t)(q0 + row)*HDIM + ch*8);
    }
    CPCOMMIT();
    CPWAIT0();
    __syncthreads();

    uint32_t qf[4][4];
    {
        int row = 16*wid + (l & 15);
        #pragma unroll
        for (int kc = 0; kc < 4; kc++) {
            int ko = kc*16 + ((l >> 4) << 3);
            uint32_t off = (uint32_t)(row*APITCH + ko*2);
            ldsm4(qf[kc][0],qf[kc][1],qf[kc][2],qf[kc][3], sb + off);
        }
    }
    __syncthreads();   // all warps done reading Q before buffer reuse

    auto load_kv = [&](int kt){
        const uint32_t stb = sb + (kt & 1)*ASTAGE;
        const int k0 = kt * 64;
        #pragma unroll
        for (int i = 0; i < 8; i++) {
            int g = i*128 + tid;
            int p = g >> 9, row = (g >> 3) & 63, ch = g & 7;  // p: 0 K, 1 V
            const __half* src = p ? Vg : Kg;
            cpa16(stb + p*AKPL + row*APITCH + ch*16,
                  src + (size_t)(k0 + row)*HDIM + ch*8);
        }
        CPCOMMIT();
    };
    load_kv(0);
    CPWAIT0();
    __syncthreads();

    float o[8][4];
    #pragma unroll
    for (int t = 0; t < 8; t++)
        #pragma unroll
        for (int j = 0; j < 4; j++) o[t][j] = 0.f;
    float mr0 = -1e30f, mr1 = -1e30f, lr0 = 0.f, lr1 = 0.f;
    const int qg0 = q0 + 16*wid + (l >> 2);
    const int qg1 = qg0 + 8;

    for (int kt = 0; kt < nkt; kt++) {
        if (kt + 1 < nkt) load_kv(kt + 1);
        const uint32_t stb = sb + (kt & 1)*ASTAGE;
        const int k0 = kt * 64;

        {
            // ---- S = Q K^T ----
            float s[8][4];
            #pragma unroll
            for (int t = 0; t < 8; t++)
                #pragma unroll
                for (int j = 0; j < 4; j++) s[t][j] = 0.f;
            #pragma unroll
            for (int kc = 0; kc < 4; kc++) {
                uint32_t bf[8][2];
                #pragma unroll
                for (int tp = 0; tp < 4; tp++) {
                    int nrow = 16*tp + ((l>>4)<<3) + (l & 7);
                    int ko   = kc*16 + (((l>>3)&1) << 3);
                    uint32_t off = (uint32_t)(nrow*APITCH + ko*2);
                    ldsm4(bf[2*tp][0],bf[2*tp][1],bf[2*tp+1][0],bf[2*tp+1][1], stb + off);
                }
                #pragma unroll
                for (int t = 0; t < 8; t++) mma_fp16(s[t], qf[kc], bf[t]);
            }
            // ---- causal mask (only near diagonal) ----
            if (k0 + 63 > qg0) {
                #pragma unroll
                for (int t = 0; t < 8; t++) {
                    int kg = k0 + 8*t + 2*(l & 3);
                    if (kg     > qg0) s[t][0] = -1e30f;
                    if (kg + 1 > qg0) s[t][1] = -1e30f;
                    if (kg     > qg1) s[t][2] = -1e30f;
                    if (kg + 1 > qg1) s[t][3] = -1e30f;
                }
            }
            // ---- online softmax (rows qg0, qg1) ----
            float mx0 = -1e30f, mx1 = -1e30f;
            #pragma unroll
            for (int t = 0; t < 8; t++) {
                mx0 = fmaxf(mx0, fmaxf(s[t][0], s[t][1]));
                mx1 = fmaxf(mx1, fmaxf(s[t][2], s[t][3]));
            }
            mx0 = fmaxf(mx0, __shfl_xor_sync(0xffffffffu, mx0, 1));
            mx0 = fmaxf(mx0, __shfl_xor_sync(0xffffffffu, mx0, 2));
            mx1 = fmaxf(mx1, __shfl_xor_sync(0xffffffffu, mx1, 1));
            mx1 = fmaxf(mx1, __shfl_xor_sync(0xffffffffu, mx1, 2));
            float mn0 = fmaxf(mr0, mx0), mn1 = fmaxf(mr1, mx1);
            float a0 = fexp(mr0 - mn0), a1 = fexp(mr1 - mn1);
            mr0 = mn0; mr1 = mn1;
            float rs0 = 0.f, rs1 = 0.f;
            #pragma unroll
            for (int t = 0; t < 8; t++) {
                s[t][0] = fexp(s[t][0] - mn0);
                s[t][1] = fexp(s[t][1] - mn0);
                s[t][2] = fexp(s[t][2] - mn1);
                s[t][3] = fexp(s[t][3] - mn1);
                rs0 += s[t][0] + s[t][1];
                rs1 += s[t][2] + s[t][3];
            }
            rs0 += __shfl_xor_sync(0xffffffffu, rs0, 1);
            rs0 += __shfl_xor_sync(0xffffffffu, rs0, 2);
            rs1 += __shfl_xor_sync(0xffffffffu, rs1, 1);
            rs1 += __shfl_xor_sync(0xffffffffu, rs1, 2);
            lr0 = lr0*a0 + rs0;
            lr1 = lr1*a1 + rs1;
            #pragma unroll
            for (int t = 0; t < 8; t++) {
                o[t][0] *= a0; o[t][1] *= a0; o[t][2] *= a1; o[t][3] *= a1;
            }
            // ---- P -> fp16 A-fragments (registers only) ----
            uint32_t ph[4][4];
            #pragma unroll
            for (int kc = 0; kc < 4; kc++) {
                int t0 = 2*kc, t1 = t0 + 1;
                ph[kc][0] = pack2h(s[t0][0], s[t0][1]);
                ph[kc][1] = pack2h(s[t0][2], s[t0][3]);
                ph[kc][2] = pack2h(s[t1][0], s[t1][1]);
                ph[kc][3] = pack2h(s[t1][2], s[t1][3]);
            }
            // ---- O += P V, V via ldmatrix.trans ----
            #pragma unroll
            for (int kc = 0; kc < 4; kc++) {
                uint32_t vf[8][2];
                #pragma unroll
                for (int tp = 0; tp < 4; tp++) {
                    int row = kc*16 + ((l>>3)&1)*8 + (l & 7);
                    int co  = 16*tp + ((l >> 4) << 3);
                    uint32_t off = (uint32_t)(row*APITCH + co*2);
                    ldsm4t(vf[2*tp][0],vf[2*tp][1],vf[2*tp+1][0],vf[2*tp+1][1], stb + AKPL + off);
                }
                #pragma unroll
                for (int t = 0; t < 8; t++) mma_fp16(o[t], ph[kc], vf[t]);
            }
        }
        if (kt + 1 < nkt) { CPWAIT0(); __syncthreads(); }
    }

    // ---- epilogue: normalize, write fp16 plane [B,S,E] ----
    const float inv0 = 1.f / lr0, inv1 = 1.f / lr1;
    const int b = bh >> 4, h = bh & 15;
    const int s0 = qg0, s1 = qg1;
    #pragma unroll
    for (int t = 0; t < 8; t++) {
        int d = 8*t + 2*(l & 3);
        int e = h*HDIM + d;
        *(uint32_t*)(g_a + ((size_t)b*SEQ + s0)*EMBED + e) =
            pack2h(o[t][0]*inv0, o[t][1]*inv0);
        *(uint32_t*)(g_a + ((size_t)b*SEQ + s1)*EMBED + e) =
            pack2h(o[t][2]*inv1, o[t][3]*inv1);
    }
}

// ---------------------------------------------------------------------------
extern "C" void kernel_launch(void* const* d_in, const int* in_sizes, int n_in,
                              void* d_out, int out_size)
{
    const float* x  = (const float*)d_in[0];
    const float* Wq = (const float*)d_in[1];
    const float* Wk = (const float*)d_in[2];
    const float* Wv = (const float*)d_in[3];
    const float* Wo = (const float*)d_in[4];
    const float* bo = (const float*)d_in[5];
    float* out = (float*)d_out;

    cudaFuncSetAttribute(gemm_kernel, cudaFuncAttributeMaxDynamicSharedMemorySize, GSMEM);
    cudaFuncSetAttribute(attn_kernel, cudaFuncAttributeMaxDynamicSharedMemorySize, ASMEM);

    prep_kernel<<<dim3(32, 32, 8), dim3(32, 8)>>>(x, Wq, Wk, Wv, Wo);

    gemm_kernel<<<dim3(4, 32, 3), 512, GSMEM>>>(nullptr, nullptr, 0);  // QKV
    attn_kernel<<<dim3(32, 32), 128, ASMEM>>>();                       // attention
    gemm_kernel<<<dim3(4, 32, 1), 512, GSMEM>>>(out, bo, 1);           // O-proj
}

// round 14
// speedup vs baseline: 2.4490x; 1.0316x over previous
#include <cuda_runtime.h>
#include <cuda_fp16.h>
#include <cstdint>
#include <math.h>

#define BATCH  2
#define SEQ    2048
#define EMBED  1024
#define NHEADS 16
#define HDIM   64
#define MROWS  4096
#define MATSZ  (MROWS*EMBED)     // 4194304
#define WSZ    (EMBED*EMBED)     // 1048576

// ---------------------------------------------------------------------------
// Scratch planes (__device__ globals; allocation-free rule)
// Plain fp16 single-term pipeline (fp32 accumulate in all MMAs).
// ---------------------------------------------------------------------------
__device__ __half g_x[MATSZ];          // x fp16 [M,K]
__device__ __half g_wt[4*WSZ];         // W^T fp16 [N,K] (q,k,v,o)
__device__ __half g_qkv[3*MATSZ];      // q,k,v fp16 [B,H,S,D]
__device__ __half g_a[MATSZ];          // attn out fp16 [M,E]

// ---------------------------------------------------------------------------
// Helpers
// ---------------------------------------------------------------------------
__device__ __forceinline__ uint32_t s2u(const void* p){
    uint32_t a;
    asm("{ .reg .u64 t; cvta.to.shared.u64 t, %1; cvt.u32.u64 %0, t; }" : "=r"(a) : "l"(p));
    return a;
}
__device__ __forceinline__ uint32_t pack2h(float lo, float hi){
    __half2 v = __halves2half2(__float2half(lo), __float2half(hi));
    return *reinterpret_cast<uint32_t*>(&v);
}
__device__ __forceinline__ void ldsm4(uint32_t& r0,uint32_t& r1,uint32_t& r2,uint32_t& r3,uint32_t a){
    asm volatile("ldmatrix.sync.aligned.m8n8.x4.shared.b16 {%0,%1,%2,%3}, [%4];"
        : "=r"(r0),"=r"(r1),"=r"(r2),"=r"(r3) : "r"(a));
}
__device__ __forceinline__ void ldsm4t(uint32_t& r0,uint32_t& r1,uint32_t& r2,uint32_t& r3,uint32_t a){
    asm volatile("ldmatrix.sync.aligned.m8n8.x4.trans.shared.b16 {%0,%1,%2,%3}, [%4];"
        : "=r"(r0),"=r"(r1),"=r"(r2),"=r"(r3) : "r"(a));
}
__device__ __forceinline__ void mma_fp16(float* c, const uint32_t* a, const uint32_t* b){
    asm volatile("mma.sync.aligned.m16n8k16.row.col.f32.f16.f16.f32 "
        "{%0,%1,%2,%3}, {%4,%5,%6,%7}, {%8,%9}, {%0,%1,%2,%3};"
        : "+f"(c[0]),"+f"(c[1]),"+f"(c[2]),"+f"(c[3])
        : "r"(a[0]),"r"(a[1]),"r"(a[2]),"r"(a[3]), "r"(b[0]),"r"(b[1]));
}
__device__ __forceinline__ void cpa16(uint32_t dst, const void* src){
    asm volatile("cp.async.cg.shared.global [%0], [%1], 16;" :: "r"(dst), "l"(src));
}
#define CPCOMMIT() asm volatile("cp.async.commit_group;" ::: "memory")
#define CPWAIT0()  asm volatile("cp.async.wait_group 0;" ::: "memory")

// FMA-only exp (x <= 0 path): ~3e-6 rel err, no MUFU.
__device__ __forceinline__ float fexp(float x){
    float y = x * 1.4426950408889634f;
    y = fmaxf(y, -126.0f);
    float t = y + 12582912.0f;               // round-to-nearest
    int   n = __float_as_int(t) - 0x4B400000;
    float f = y - (t - 12582912.0f);         // f in [-0.5, 0.5]
    float p = 1.3333558146e-3f;
    p = fmaf(p, f, 9.6181291076e-3f);
    p = fmaf(p, f, 5.5504108665e-2f);
    p = fmaf(p, f, 2.4022650696e-1f);
    p = fmaf(p, f, 6.9314718056e-1f);
    p = fmaf(p, f, 1.0f);
    return __int_as_float(__float_as_int(p) + (n << 23));
}

// ---------------------------------------------------------------------------
// Fused prep: z 0..3 -> transpose W (q,k,v,o) to fp16; z 4..7 -> convert x
// block = (32, 8) = 256 threads
// ---------------------------------------------------------------------------
__global__ __launch_bounds__(256) void prep_kernel(
    const float* __restrict__ x,
    const float* __restrict__ Wq, const float* __restrict__ Wk,
    const float* __restrict__ Wv, const float* __restrict__ Wo)
{
    __shared__ float t[32][33];
    const int z = blockIdx.z;
    const int tx = threadIdx.x, ty = threadIdx.y;

    if (z >= 4) {
        int b = (z - 4)*1024 + blockIdx.y*32 + blockIdx.x;
        int i = b*256 + ty*32 + tx;
        float4 v = ((const float4*)x)[i];
        ((uint2*)g_x)[i] = make_uint2(pack2h(v.x, v.y), pack2h(v.z, v.w));
        return;
    }

    const float* W = (z==0)?Wq:(z==1)?Wk:(z==2)?Wv:Wo;
    __half* O = g_wt + (size_t)z*WSZ;
    int nb = blockIdx.x*32, kb = blockIdx.y*32;
    #pragma unroll
    for (int r = 0; r < 4; r++)
        t[ty + r*8][tx] = W[(size_t)(kb + ty + r*8)*EMBED + nb + tx];
    __syncthreads();
    #pragma unroll
    for (int r = 0; r < 4; r++)
        O[(size_t)(nb + ty + r*8)*EMBED + kb + tx] = __float2half(t[tx][ty + r*8]);
}

// ---------------------------------------------------------------------------
// mma.sync fp16 GEMM: D[M,N] = A[M,K] @ B^T[N,K]
// CTA 128x256, 512 threads, 16 warps (4m x 4n), warp 32x64, KC=64, 2-stage.
// KC=64 halves per-chunk barrier/wait overhead (16 chunks).
// mode 0: A = x, B = W_{q,k,v}(z); epilogue -> fp16 qkv planes
// mode 1: A = attn out, B = W_o; epilogue -> fp32 out + bias
// ---------------------------------------------------------------------------
#define GKC 64
#define GNCH (EMBED/GKC)         // 16 chunks
#define GPITCH 144
#define GAPL  (128*GPITCH)       // 18432 (A plane)
#define GBPL  (256*GPITCH)       // 36864 (B plane)
#define GB_OFF GAPL
#define GSTAGE (GAPL + GBPL)     // 55296
#define GSMEM  (2*GSTAGE)        // 110592

__global__ __launch_bounds__(512,1) void gemm_kernel(float* __restrict__ out,
                                                     const float* __restrict__ bias,
                                                     int mode)
{
    extern __shared__ char smg[];
    const uint32_t sb = s2u(smg);
    const int tid = threadIdx.x, l = tid & 31, wid = tid >> 5;
    const int wm = wid >> 2, wn = wid & 3;
    const int m0 = blockIdx.y * 128, n0 = blockIdx.x * 256;
    const int z = blockIdx.z;

    const __half *Ap, *Bp;
    if (mode == 0) { Ap = g_x; Bp = g_wt + (size_t)z*WSZ; }
    else           { Ap = g_a; Bp = g_wt + 3*(size_t)WSZ; }

    auto load_stage = [&](int c){
        const uint32_t sbase = sb + (c & 1)*GSTAGE;
        const int k0 = c * GKC;
        #pragma unroll
        for (int i = 0; i < 2; i++) {        // A: 128 rows x 8 ch = 1024
            int g   = i*512 + tid;
            int row = g >> 3;
            int ch  = g & 7;
            cpa16(sbase + row*GPITCH + ch*16,
                  Ap + (size_t)(m0 + row)*EMBED + k0 + ch*8);
        }
        #pragma unroll
        for (int i = 0; i < 4; i++) {        // B: 256 rows x 8 ch = 2048
            int g   = i*512 + tid;
            int row = (g >> 3) & 255;
            int ch  = g & 7;
            cpa16(sbase + GB_OFF + row*GPITCH + ch*16,
                  Bp + (size_t)(n0 + row)*EMBED + k0 + ch*8);
        }
        CPCOMMIT();
    };

    float acc[2][8][4];
    #pragma unroll
    for (int i = 0; i < 2; i++)
        #pragma unroll
        for (int t = 0; t < 8; t++)
            #pragma unroll
            for (int j = 0; j < 4; j++) acc[i][t][j] = 0.f;

    load_stage(0);
    for (int c = 0; c < GNCH; c++) {
        CPWAIT0();
        __syncthreads();
        if (c + 1 < GNCH) load_stage(c + 1);
        const uint32_t stb = sb + (c & 1)*GSTAGE;
        #pragma unroll
        for (int kk = 0; kk < 4; kk++) {
            uint32_t ah[2][4], bf[8][2];
            #pragma unroll
            for (int i = 0; i < 2; i++) {
                int row = 32*wm + 16*i + (l & 15);
                int ko  = kk*16 + ((l >> 4) << 3);
                uint32_t off = (uint32_t)(row*GPITCH + ko*2);
                ldsm4(ah[i][0],ah[i][1],ah[i][2],ah[i][3], stb + off);
            }
            #pragma unroll
            for (int tp = 0; tp < 4; tp++) {
                int nrow = 64*wn + 16*tp + ((l>>4)<<3) + (l & 7);
                int ko   = kk*16 + (((l>>3)&1) << 3);
                uint32_t off = (uint32_t)(nrow*GPITCH + ko*2);
                ldsm4(bf[2*tp][0],bf[2*tp][1],bf[2*tp+1][0],bf[2*tp+1][1],
                      stb + GB_OFF + off);
            }
            #pragma unroll
            for (int i = 0; i < 2; i++)
                #pragma unroll
                for (int t = 0; t < 8; t++) mma_fp16(acc[i][t], ah[i], bf[t]);
        }
    }

    // epilogue
    if (mode == 1) {
        #pragma unroll
        for (int i = 0; i < 2; i++)
            #pragma unroll
            for (int t = 0; t < 8; t++)
                #pragma unroll
                for (int rr = 0; rr < 2; rr++) {
                    int m = m0 + 32*wm + 16*i + (l>>2) + 8*rr;
                    int n = n0 + 64*wn + 8*t + 2*(l&3);
                    float2 v = make_float2(acc[i][t][2*rr]   + bias[n],
                                           acc[i][t][2*rr+1] + bias[n+1]);
                    *(float2*)&out[(size_t)m*EMBED + n] = v;
                }
    } else {
        __half* oh = g_qkv + (size_t)z*MATSZ;
        const float scl = (z == 0) ? 0.125f : 1.0f;   // fold 1/sqrt(D) into Q
        #pragma unroll
        for (int i = 0; i < 2; i++)
            #pragma unroll
            for (int t = 0; t < 8; t++)
                #pragma unroll
                for (int rr = 0; rr < 2; rr++) {
                    int m = m0 + 32*wm + 16*i + (l>>2) + 8*rr;
                    int n = n0 + 64*wn + 8*t + 2*(l&3);
                    uint32_t h = pack2h(acc[i][t][2*rr]*scl, acc[i][t][2*rr+1]*scl);
                    int b = m >> 11, s = m & 2047, hh = n >> 6, d = n & 63;
                    size_t idx = ((((size_t)b*NHEADS + hh)*SEQ) + s)*HDIM + d;
                    *(uint32_t*)(oh + idx) = h;
                }
    }
}

// ---------------------------------------------------------------------------
// Flash attention, plain fp16. CTA = 64 q-rows; 4 warps; 3 CTAs/SM.
// K-tile = 128 keys: halves softmax passes / barriers vs 64.
// S = Q K^T, O += P V, fp32 accumulate + fp32 softmax.
// ---------------------------------------------------------------------------
#define APITCH 144
#define AKPL   (128*APITCH)        // 18432 (one plane: 128 rows)
#define ASTAGE (2*AKPL)            // 36864 (K, V)
#define ASMEM  (2*ASTAGE)          // 73728

__global__ __launch_bounds__(128,3) void attn_kernel()
{
    extern __shared__ char sma[];
    const uint32_t sb = s2u(sma);
    const int tid = threadIdx.x, l = tid & 31, wid = tid >> 5;
    const int qt = 31 - (int)blockIdx.x;        // heavy tiles first
    const int bh = blockIdx.y;
    const int q0 = qt * 64;
    const int nkt = (q0 + 63)/128 + 1;          // 128-key tiles
    const size_t base = (size_t)bh * SEQ * HDIM;
    const __half *Qg = g_qkv + base;
    const __half *Kg = g_qkv + MATSZ + base;
    const __half *Vg = g_qkv + 2*(size_t)MATSZ + base;

    // ---- stream Q plane through stage-0 buffer, extract register frags ----
    #pragma unroll
    for (int i = 0; i < 4; i++) {
        int g = i*128 + tid;
        int row = (g >> 3) & 63, ch = g & 7;
        cpa16(sb + row*APITCH + ch*16, Qg + (size_t)(q0 + row)*HDIM + ch*8);
    }
    CPCOMMIT();
    CPWAIT0();
    __syncthreads();

    uint32_t qf[4][4];
    {
        int row = 16*wid + (l & 15);
        #pragma unroll
        for (int kc = 0; kc < 4; kc++) {
            int ko = kc*16 + ((l >> 4) << 3);
            uint32_t off = (uint32_t)(row*APITCH + ko*2);
            ldsm4(qf[kc][0],qf[kc][1],qf[kc][2],qf[kc][3], sb + off);
        }
    }
    __syncthreads();   // all warps done reading Q before buffer reuse

    auto load_kv = [&](int kt){
        const uint32_t stb = sb + (kt & 1)*ASTAGE;
        const int k0 = kt * 128;
        #pragma unroll
        for (int i = 0; i < 16; i++) {
            int g = i*128 + tid;
            int p = g >> 10, row = (g >> 3) & 127, ch = g & 7;  // p: 0 K, 1 V
            const __half* src = p ? Vg : Kg;
            cpa16(stb + p*AKPL + row*APITCH + ch*16,
                  src + (size_t)(k0 + row)*HDIM + ch*8);
        }
        CPCOMMIT();
    };
    load_kv(0);
    CPWAIT0();
    __syncthreads();

    float o[8][4];
    #pragma unroll
    for (int t = 0; t < 8; t++)
        #pragma unroll
        for (int j = 0; j < 4; j++) o[t][j] = 0.f;
    float mr0 = -1e30f, mr1 = -1e30f, lr0 = 0.f, lr1 = 0.f;
    const int qg0 = q0 + 16*wid + (l >> 2);
    const int qg1 = qg0 + 8;

    for (int kt = 0; kt < nkt; kt++) {
        if (kt + 1 < nkt) load_kv(kt + 1);
        const uint32_t stb = sb + (kt & 1)*ASTAGE;
        const int k0 = kt * 128;

        {
            // ---- S = Q K^T over 128 keys (16 n8-tiles) ----
            float s[16][4];
            #pragma unroll
            for (int t = 0; t < 16; t++)
                #pragma unroll
                for (int j = 0; j < 4; j++) s[t][j] = 0.f;
            #pragma unroll
            for (int kc = 0; kc < 4; kc++) {
                #pragma unroll
                for (int half = 0; half < 2; half++) {   // bf regs capped at 16
                    uint32_t bf[8][2];
                    #pragma unroll
                    for (int tp = 0; tp < 4; tp++) {
                        int nrow = half*64 + 16*tp + ((l>>4)<<3) + (l & 7);
                        int ko   = kc*16 + (((l>>3)&1) << 3);
                        uint32_t off = (uint32_t)(nrow*APITCH + ko*2);
                        ldsm4(bf[2*tp][0],bf[2*tp][1],bf[2*tp+1][0],bf[2*tp+1][1], stb + off);
                    }
                    #pragma unroll
                    for (int t = 0; t < 8; t++) mma_fp16(s[half*8 + t], qf[kc], bf[t]);
                }
            }
            // ---- causal mask (only near diagonal) ----
            if (k0 + 127 > qg0) {
                #pragma unroll
                for (int t = 0; t < 16; t++) {
                    int kg = k0 + 8*t + 2*(l & 3);
                    if (kg     > qg0) s[t][0] = -1e30f;
                    if (kg + 1 > qg0) s[t][1] = -1e30f;
                    if (kg     > qg1) s[t][2] = -1e30f;
                    if (kg + 1 > qg1) s[t][3] = -1e30f;
                }
            }
            // ---- online softmax (rows qg0, qg1) ----
            float mx0 = -1e30f, mx1 = -1e30f;
            #pragma unroll
            for (int t = 0; t < 16; t++) {
                mx0 = fmaxf(mx0, fmaxf(s[t][0], s[t][1]));
                mx1 = fmaxf(mx1, fmaxf(s[t][2], s[t][3]));
            }
            mx0 = fmaxf(mx0, __shfl_xor_sync(0xffffffffu, mx0, 1));
            mx0 = fmaxf(mx0, __shfl_xor_sync(0xffffffffu, mx0, 2));
            mx1 = fmaxf(mx1, __shfl_xor_sync(0xffffffffu, mx1, 1));
            mx1 = fmaxf(mx1, __shfl_xor_sync(0xffffffffu, mx1, 2));
            float mn0 = fmaxf(mr0, mx0), mn1 = fmaxf(mr1, mx1);
            float a0 = fexp(mr0 - mn0), a1 = fexp(mr1 - mn1);
            mr0 = mn0; mr1 = mn1;
            float rs0 = 0.f, rs1 = 0.f;
            #pragma unroll
            for (int t = 0; t < 16; t++) {
                s[t][0] = fexp(s[t][0] - mn0);
                s[t][1] = fexp(s[t][1] - mn0);
                s[t][2] = fexp(s[t][2] - mn1);
                s[t][3] = fexp(s[t][3] - mn1);
                rs0 += s[t][0] + s[t][1];
                rs1 += s[t][2] + s[t][3];
            }
            rs0 += __shfl_xor_sync(0xffffffffu, rs0, 1);
            rs0 += __shfl_xor_sync(0xffffffffu, rs0, 2);
            rs1 += __shfl_xor_sync(0xffffffffu, rs1, 1);
            rs1 += __shfl_xor_sync(0xffffffffu, rs1, 2);
            lr0 = lr0*a0 + rs0;
            lr1 = lr1*a1 + rs1;
            #pragma unroll
            for (int t = 0; t < 8; t++) {
                o[t][0] *= a0; o[t][1] *= a0; o[t][2] *= a1; o[t][3] *= a1;
            }
            // ---- P -> fp16 A-fragments (registers only), 8 k16 chunks ----
            uint32_t ph[8][4];
            #pragma unroll
            for (int kc = 0; kc < 8; kc++) {
                int t0 = 2*kc, t1 = t0 + 1;
                ph[kc][0] = pack2h(s[t0][0], s[t0][1]);
                ph[kc][1] = pack2h(s[t0][2], s[t0][3]);
                ph[kc][2] = pack2h(s[t1][0], s[t1][1]);
                ph[kc][3] = pack2h(s[t1][2], s[t1][3]);
            }
            // ---- O += P V over 128 keys, V via ldmatrix.trans ----
            #pragma unroll
            for (int kc = 0; kc < 8; kc++) {
                uint32_t vf[8][2];
                #pragma unroll
                for (int tp = 0; tp < 4; tp++) {
                    int row = kc*16 + ((l>>3)&1)*8 + (l & 7);
                    int co  = 16*tp + ((l >> 4) << 3);
                    uint32_t off = (uint32_t)(row*APITCH + co*2);
                    ldsm4t(vf[2*tp][0],vf[2*tp][1],vf[2*tp+1][0],vf[2*tp+1][1], stb + AKPL + off);
                }
                #pragma unroll
                for (int t = 0; t < 8; t++) mma_fp16(o[t], ph[kc], vf[t]);
            }
        }
        if (kt + 1 < nkt) { CPWAIT0(); __syncthreads(); }
    }

    // ---- epilogue: normalize, write fp16 plane [B,S,E] ----
    const float inv0 = 1.f / lr0, inv1 = 1.f / lr1;
    const int b = bh >> 4, h = bh & 15;
    const int s0 = qg0, s1 = qg1;
    #pragma unroll
    for (int t = 0; t < 8; t++) {
        int d = 8*t + 2*(l & 3);
        int e = h*HDIM + d;
        *(uint32_t*)(g_a + ((size_t)b*SEQ + s0)*EMBED + e) =
            pack2h(o[t][0]*inv0, o[t][1]*inv0);
        *(uint32_t*)(g_a + ((size_t)b*SEQ + s1)*EMBED + e) =
            pack2h(o[t][2]*inv1, o[t][3]*inv1);
    }
}

// ---------------------------------------------------------------------------
extern "C" void kernel_launch(void* const* d_in, const int* in_sizes, int n_in,
                              void* d_out, int out_size)
{
    const float* x  = (const float*)d_in[0];
    const float* Wq = (const float*)d_in[1];
    const float* Wk = (const float*)d_in[2];
    const float* Wv = (const float*)d_in[3];
    const float* Wo = (const float*)d_in[4];
    const float* bo = (const float*)d_in[5];
    float* out = (float*)d_out;

    cudaFuncSetAttribute(gemm_kernel, cudaFuncAttributeMaxDynamicSharedMemorySize, GSMEM);
    cudaFuncSetAttribute(attn_kernel, cudaFuncAttributeMaxDynamicSharedMemorySize, ASMEM);

    prep_kernel<<<dim3(32, 32, 8), dim3(32, 8)>>>(x, Wq, Wk, Wv, Wo);

    gemm_kernel<<<dim3(4, 32, 3), 512, GSMEM>>>(nullptr, nullptr, 0);  // QKV
    attn_kernel<<<dim3(32, 32), 128, ASMEM>>>();                       // attention
    gemm_kernel<<<dim3(4, 32, 1), 512, GSMEM>>>(out, bo, 1);           // O-proj
}